// round 14
// baseline (speedup 1.0000x reference)
#include <cuda_runtime.h>
#include <cuda_fp16.h>
#include <cuda_bf16.h>
#include <math.h>
#include <stdint.h>

#define HEADS  8
#define LEVELS 4
#define POINTS 4
#define DIM    32
#define EMBED  256
#define NQ     1200
#define BS     8
#define NV     19560   // 92*160 + 46*80 + 23*40 + 12*20

#define OFF_N  256
#define QO_N   384

#define NCHUNK 4                    // batch chunks (2 batches each)
#define CH_ROWS_V (2 * NV)          // value rows per chunk
#define CH_ROWS_Q (2 * NQ)          // query rows per chunk

// Scratch (allocation-free rule: device globals)
__device__ __half    g_v_h[(size_t)BS * HEADS * NV * DIM]; // (b,h,pix,d) fp16 : 80 MB
__device__ float     g_qo[(size_t)BS * NQ * QO_N];         // offsets(256) || logits(128)
__device__ float     g_att[(size_t)BS * NQ * EMBED];
__device__ uint32_t  g_wvT[256 * 128];                     // Wv bf16 pairs [n][kk]

__constant__ int   c_H[4]    = {92, 46, 23, 12};
__constant__ int   c_W[4]    = {160, 80, 40, 20};
__constant__ int   c_start[4]= {0, 14720, 18400, 19320};
__constant__ float c_Hf[4]   = {92.f, 46.f, 23.f, 12.f};
__constant__ float c_Wf[4]   = {160.f, 80.f, 40.f, 20.f};
__constant__ float c_invH[4] = {1.f/92.f, 1.f/46.f, 1.f/23.f, 1.f/12.f};
__constant__ float c_invW[4] = {1.f/160.f, 1.f/80.f, 1.f/40.f, 1.f/20.f};

// ---------------------------------------------------------------------------
__global__ __launch_bounds__(256)
void conv_wv(const float* __restrict__ Wv)
{
    int idx = blockIdx.x * 256 + threadIdx.x;
    int n  = idx >> 7;
    int kk = idx & 127;
    float lo = Wv[(size_t)(2 * kk) * 256 + n];
    float hi = Wv[(size_t)(2 * kk + 1) * 256 + n];
    __nv_bfloat162 p = __floats2bfloat162_rn(lo, hi);
    g_wvT[n * 128 + kk] = *reinterpret_cast<uint32_t*>(&p);
}

// ===========================================================================
// bf16 mma.m16n8k16 value GEMM (R9 config + row-base param for chunking).
// ===========================================================================
__device__ __forceinline__ void mma_bf16(float& d0, float& d1, float& d2, float& d3,
                                         uint32_t a0, uint32_t a1, uint32_t a2, uint32_t a3,
                                         uint32_t b0, uint32_t b1) {
    asm volatile("mma.sync.aligned.m16n8k16.row.col.f32.bf16.bf16.f32 "
                 "{%0,%1,%2,%3},{%4,%5,%6,%7},{%8,%9},{%0,%1,%2,%3};"
                 : "+f"(d0), "+f"(d1), "+f"(d2), "+f"(d3)
                 : "r"(a0), "r"(a1), "r"(a2), "r"(a3), "r"(b0), "r"(b1));
}

__device__ __forceinline__ void ldsm_x4(uint32_t& r0, uint32_t& r1, uint32_t& r2, uint32_t& r3,
                                        uint32_t addr) {
    asm volatile("ldmatrix.sync.aligned.m8n8.x4.shared.b16 {%0,%1,%2,%3}, [%4];"
                 : "=r"(r0), "=r"(r1), "=r"(r2), "=r"(r3) : "r"(addr));
}

__device__ __forceinline__ uint32_t smem_u32(const void* p) {
    uint32_t a;
    asm("{ .reg .u64 t; cvta.to.shared.u64 t, %1; cvt.u32.u64 %0, t; }" : "=r"(a) : "l"(p));
    return a;
}

#define PSTRIDE 20
#define STG_ROW 40

__global__ __launch_bounds__(256)
void gemm_v_bf16(const float* __restrict__ A, const float* __restrict__ bias,
                 int base, int M)
{
    __shared__ uint32_t As[128][PSTRIDE];
    __shared__ uint32_t Bsm[128][PSTRIDE];

    const int tid  = threadIdx.x;
    const int lane = tid & 31;
    const int warp = tid >> 5;
    const int wm   = warp >> 2;
    const int wn   = warp & 3;
    const int tg   = lane >> 2;
    const int tig  = lane & 3;

    const int block_m = base + blockIdx.y * 128;
    const int block_n = blockIdx.x * 128;

    float acc[4][4][4];
#pragma unroll
    for (int i = 0; i < 4; i++)
#pragma unroll
        for (int j = 0; j < 4; j++)
#pragma unroll
            for (int r = 0; r < 4; r++) acc[i][j][r] = 0.f;

    float4 aS[4];
    uint4  bU[2];

    const int a_row0 = tid >> 3;
    const int a_c4   = (tid & 7) * 4;
    const int b_n    = tid >> 1;
    const int b_s0   = (tid & 1) * 2;

    uint32_t aAddr[4];
    {
        uint32_t bbase = smem_u32(As);
        int row = wm * 64 + (lane & 15);
        int po  = (lane >> 4) * 4;
#pragma unroll
        for (int mt = 0; mt < 4; mt++)
            aAddr[mt] = bbase + (uint32_t)(((row + mt * 16) * PSTRIDE + po) * 4);
    }
    uint32_t bAddr[2];
    {
        uint32_t bbase = smem_u32(Bsm);
        int row = wn * 32 + (lane & 7) + ((lane >> 4) & 1) * 8;
        int po  = ((lane >> 3) & 1) * 4;
#pragma unroll
        for (int g = 0; g < 2; g++)
            bAddr[g] = bbase + (uint32_t)(((row + g * 16) * PSTRIDE + po) * 4);
    }

    auto ldgA = [&](int k0) {
#pragma unroll
        for (int i = 0; i < 4; i++) {
            int gr = block_m + a_row0 + i * 32;
            float4 v = make_float4(0.f, 0.f, 0.f, 0.f);
            if (gr < M)
                v = *reinterpret_cast<const float4*>(A + (size_t)gr * 256 + k0 + a_c4);
            aS[i] = v;
        }
    };
    auto ldgB = [&](int k0) {
        int kk0 = k0 >> 1;
#pragma unroll
        for (int j = 0; j < 2; j++)
            bU[j] = *reinterpret_cast<const uint4*>(
                &g_wvT[(block_n + b_n) * 128 + kk0 + (b_s0 + j) * 4]);
    };
    auto sts = [&]() {
#pragma unroll
        for (int i = 0; i < 4; i++) {
            __nv_bfloat162 p0 = __floats2bfloat162_rn(aS[i].x, aS[i].y);
            __nv_bfloat162 p1 = __floats2bfloat162_rn(aS[i].z, aS[i].w);
            uint2 u;
            u.x = *reinterpret_cast<uint32_t*>(&p0);
            u.y = *reinterpret_cast<uint32_t*>(&p1);
            *reinterpret_cast<uint2*>(&As[a_row0 + i * 32][(a_c4 >> 1)]) = u;
        }
#pragma unroll
        for (int j = 0; j < 2; j++)
            *reinterpret_cast<uint4*>(&Bsm[b_n][(b_s0 + j) * 4]) = bU[j];
    };

    ldgA(0); ldgB(0);

    for (int k0 = 0; k0 < 256; k0 += 32) {
        sts();
        __syncthreads();
        if (k0 + 32 < 256) { ldgA(k0 + 32); ldgB(k0 + 32); }

#pragma unroll
        for (int s = 0; s < 2; s++) {
            const uint32_t soff = (uint32_t)(s * 32);
            uint32_t a[4][4], b[4][2];
#pragma unroll
            for (int mt = 0; mt < 4; mt++)
                ldsm_x4(a[mt][0], a[mt][1], a[mt][2], a[mt][3], aAddr[mt] + soff);
#pragma unroll
            for (int g = 0; g < 2; g++)
                ldsm_x4(b[2 * g][0], b[2 * g][1], b[2 * g + 1][0], b[2 * g + 1][1],
                        bAddr[g] + soff);
#pragma unroll
            for (int mt = 0; mt < 4; mt++)
#pragma unroll
                for (int nt = 0; nt < 4; nt++)
                    mma_bf16(acc[mt][nt][0], acc[mt][nt][1], acc[mt][nt][2], acc[mt][nt][3],
                             a[mt][0], a[mt][1], a[mt][2], a[mt][3],
                             b[nt][0], b[nt][1]);
        }
        __syncthreads();
    }

    // coalesced epilogue
    const int head = 4 * blockIdx.x + wn;
    __half* stg = reinterpret_cast<__half*>(As) + warp * (16 * STG_ROW);
    const float bx[4] = { bias[head * 32 + 0 * 8 + 2 * tig], bias[head * 32 + 1 * 8 + 2 * tig],
                          bias[head * 32 + 2 * 8 + 2 * tig], bias[head * 32 + 3 * 8 + 2 * tig] };
    const float by[4] = { bias[head * 32 + 0 * 8 + 2 * tig + 1], bias[head * 32 + 1 * 8 + 2 * tig + 1],
                          bias[head * 32 + 2 * 8 + 2 * tig + 1], bias[head * 32 + 3 * 8 + 2 * tig + 1] };

#pragma unroll
    for (int mt = 0; mt < 4; mt++) {
#pragma unroll
        for (int nt = 0; nt < 4; nt++) {
#pragma unroll
            for (int rr = 0; rr < 2; rr++) {
                int r = tg + rr * 8;
                __half2 v = __floats2half2_rn(acc[mt][nt][rr * 2 + 0] + bx[nt],
                                              acc[mt][nt][rr * 2 + 1] + by[nt]);
                *reinterpret_cast<__half2*>(&stg[r * STG_ROW + nt * 8 + 2 * tig]) = v;
            }
        }
        __syncwarp();
#pragma unroll
        for (int pass = 0; pass < 2; pass++) {
            int t    = pass * 32 + lane;
            int row  = t >> 2;
            int c16  = (t & 3) * 8;
            int pixr = block_m + wm * 64 + mt * 16 + row;
            if (pixr < M) {
                int b = pixr / NV;
                int n = pixr - b * NV;
                uint4 v = *reinterpret_cast<const uint4*>(&stg[row * STG_ROW + c16]);
                *reinterpret_cast<uint4*>(
                    g_v_h + ((size_t)(b * HEADS + head) * NV + n) * DIM + c16) = v;
            }
        }
        __syncwarp();
    }
}

// ===========================================================================
// tf32 mma.sync GEMM for modes 1,2 (+ row-base param).
// ===========================================================================
__device__ __forceinline__ uint32_t f2tf32(float f) {
    uint32_t u;
    asm("cvt.rna.tf32.f32 %0, %1;" : "=r"(u) : "f"(f));
    return u;
}

__device__ __forceinline__ void mma_tf32(float& d0, float& d1, float& d2, float& d3,
                                         uint32_t a0, uint32_t a1, uint32_t a2, uint32_t a3,
                                         uint32_t b0, uint32_t b1) {
    asm volatile("mma.sync.aligned.m16n8k8.row.col.f32.tf32.tf32.f32 "
                 "{%0,%1,%2,%3},{%4,%5,%6,%7},{%8,%9},{%0,%1,%2,%3};"
                 : "+f"(d0), "+f"(d1), "+f"(d2), "+f"(d3)
                 : "r"(a0), "r"(a1), "r"(a2), "r"(a3), "r"(b0), "r"(b1));
}

#define AS_STRIDE 36
#define BS_STRIDE 136

template <int MODE>
__global__ __launch_bounds__(256)
void gemm_tc(const float* __restrict__ Aext, const float* __restrict__ A2,
             const float* __restrict__ B1,  const float* __restrict__ B2,
             const float* __restrict__ bias1, const float* __restrict__ bias2,
             const float* __restrict__ addsrc, float* __restrict__ Cext,
             int base, int M)
{
    __shared__ uint32_t As[128][AS_STRIDE];
    __shared__ uint32_t Bsm[32][BS_STRIDE];

    const float* A = (MODE == 2) ? g_att : Aext;

    const int tid  = threadIdx.x;
    const int lane = tid & 31;
    const int warp = tid >> 5;
    const int wm   = warp >> 2;
    const int wn   = warp & 3;
    const int tg   = lane >> 2;
    const int tig  = lane & 3;

    const int block_m = base + blockIdx.y * 128;
    const int block_n = blockIdx.x * 128;

    float acc[4][4][4];
#pragma unroll
    for (int i = 0; i < 4; i++)
#pragma unroll
        for (int j = 0; j < 4; j++)
#pragma unroll
            for (int r = 0; r < 4; r++) acc[i][j][r] = 0.f;

    float4 aS[4], bS[4];
    const int a_row0 = tid >> 3;
    const int a_c4   = (tid & 7) * 4;
    const int b_k0   = tid >> 5;
    const int b_n4   = lane * 4;

    auto ldgA = [&](int k0) {
#pragma unroll
        for (int i = 0; i < 4; i++) {
            int gr = block_m + a_row0 + i * 32;
            float4 v = make_float4(0.f, 0.f, 0.f, 0.f);
            if (gr < M) {
                v = *reinterpret_cast<const float4*>(A + (size_t)gr * 256 + k0 + a_c4);
                if (MODE == 1) {
                    float4 v2 = *reinterpret_cast<const float4*>(A2 + (size_t)gr * 256 + k0 + a_c4);
                    v.x += v2.x; v.y += v2.y; v.z += v2.z; v.w += v2.w;
                }
            }
            aS[i] = v;
        }
    };
    auto ldgB = [&](int k0) {
#pragma unroll
        for (int i = 0; i < 4; i++) {
            int krow = b_k0 + i * 8;
            int gc   = block_n + b_n4;
            float4 v;
            if (MODE == 1) {
                if (gc < OFF_N) v = *reinterpret_cast<const float4*>(B1 + (size_t)(k0 + krow) * OFF_N + gc);
                else            v = *reinterpret_cast<const float4*>(B2 + (size_t)(k0 + krow) * 128 + (gc - OFF_N));
            } else {
                v = *reinterpret_cast<const float4*>(B1 + (size_t)(k0 + krow) * 256 + gc);
            }
            bS[i] = v;
        }
    };
    auto sts = [&]() {
#pragma unroll
        for (int i = 0; i < 4; i++) {
            uint4 u;
            u.x = f2tf32(aS[i].x); u.y = f2tf32(aS[i].y);
            u.z = f2tf32(aS[i].z); u.w = f2tf32(aS[i].w);
            *reinterpret_cast<uint4*>(&As[a_row0 + i * 32][a_c4]) = u;
        }
#pragma unroll
        for (int i = 0; i < 4; i++) {
            uint4 u;
            u.x = f2tf32(bS[i].x); u.y = f2tf32(bS[i].y);
            u.z = f2tf32(bS[i].z); u.w = f2tf32(bS[i].w);
            *reinterpret_cast<uint4*>(&Bsm[b_k0 + i * 8][b_n4]) = u;
        }
    };

    ldgA(0); ldgB(0);

    for (int k0 = 0; k0 < 256; k0 += 32) {
        sts();
        __syncthreads();
        if (k0 + 32 < 256) { ldgA(k0 + 32); ldgB(k0 + 32); }

#pragma unroll
        for (int ks = 0; ks < 4; ks++) {
            const int k = ks * 8;
            uint32_t a[4][4], b[4][2];
#pragma unroll
            for (int mt = 0; mt < 4; mt++) {
                int m = wm * 64 + mt * 16 + tg;
                a[mt][0] = As[m][k + tig];
                a[mt][1] = As[m + 8][k + tig];
                a[mt][2] = As[m][k + tig + 4];
                a[mt][3] = As[m + 8][k + tig + 4];
            }
#pragma unroll
            for (int nt = 0; nt < 4; nt++) {
                int n = wn * 32 + nt * 8 + tg;
                b[nt][0] = Bsm[k + tig][n];
                b[nt][1] = Bsm[k + tig + 4][n];
            }
#pragma unroll
            for (int mt = 0; mt < 4; mt++)
#pragma unroll
                for (int nt = 0; nt < 4; nt++)
                    mma_tf32(acc[mt][nt][0], acc[mt][nt][1], acc[mt][nt][2], acc[mt][nt][3],
                             a[mt][0], a[mt][1], a[mt][2], a[mt][3],
                             b[nt][0], b[nt][1]);
        }
        __syncthreads();
    }

#pragma unroll
    for (int mt = 0; mt < 4; mt++) {
#pragma unroll
        for (int nt = 0; nt < 4; nt++) {
            int gc = block_n + wn * 32 + nt * 8 + 2 * tig;
            float bx, by;
            if (MODE == 1) {
                bx = (gc < OFF_N) ? bias1[gc] : bias2[gc - OFF_N];
                by = (gc + 1 < OFF_N) ? bias1[gc + 1] : bias2[gc + 1 - OFF_N];
            } else {
                bx = bias1[gc]; by = bias1[gc + 1];
            }
#pragma unroll
            for (int rr = 0; rr < 2; rr++) {
                int gr = block_m + wm * 64 + mt * 16 + tg + rr * 8;
                if (gr >= M) continue;
                float ox = acc[mt][nt][rr * 2 + 0] + bx;
                float oy = acc[mt][nt][rr * 2 + 1] + by;
                if (MODE == 1) {
                    float2 o; o.x = ox; o.y = oy;
                    *reinterpret_cast<float2*>(g_qo + (size_t)gr * QO_N + gc) = o;
                } else {
                    const float2 idv = *reinterpret_cast<const float2*>(addsrc + (size_t)gr * 256 + gc);
                    float2 o; o.x = ox + idv.x; o.y = oy + idv.y;
                    *reinterpret_cast<float2*>(Cext + (size_t)gr * 256 + gc) = o;
                }
            }
        }
    }
}

// ===========================================================================
// Sampling v3 (+ bq-base param for chunking).
// ===========================================================================
__global__ __launch_bounds__(256)
void sample_kernel3(const float* __restrict__ ref, const float* __restrict__ lro,
                    int bqBase)
{
    int gwarp = (blockIdx.x * blockDim.x + threadIdx.x) >> 5;
    int lane  = threadIdx.x & 31;
    int hp    = gwarp & 3;
    int bq    = bqBase + (gwarp >> 2);
    int b  = bq / NQ;
    int hi = lane >> 4;
    int li = lane & 15;
    int h  = hp * 2 + hi;

    const float* row = g_qo + (size_t)bq * QO_N;

    float logit = row[OFF_N + h * 16 + li];
    float m = logit;
#pragma unroll
    for (int s = 8; s; s >>= 1) m = fmaxf(m, __shfl_xor_sync(0xffffffffu, m, s));
    float e = expf(logit - m);
    float ss = e;
#pragma unroll
    for (int s = 8; s; s >>= 1) ss += __shfl_xor_sync(0xffffffffu, ss, s);
    float a = e / ss;

    int l = li >> 2;
    int p = li & 3;
    int W = c_W[l], H = c_H[l], st = c_start[l];

    float rx = ref[(size_t)(bq * 4 + l) * 2 + 0];
    float ry = ref[(size_t)(bq * 4 + l) * 2 + 1];
    float lx = lro[(size_t)(bq * 8 + h) * 2 + 0];
    float ly = lro[(size_t)(bq * 8 + h) * 2 + 1];
    float ox = row[((h * 4 + l) * 4 + p) * 2 + 0];
    float oy = row[((h * 4 + l) * 4 + p) * 2 + 1];

    float px = (rx + ox * c_invW[l] + lx) * c_Wf[l] - 0.5f;
    float py = (ry + oy * c_invH[l] + ly) * c_Hf[l] - 0.5f;

    float x0f = floorf(px), y0f = floorf(py);
    int   x0  = (int)x0f,   y0  = (int)y0f;
    float wx1 = px - x0f, wx0 = 1.f - wx1;
    float wy1 = py - y0f, wy0 = 1.f - wy1;

    float vx0 = (x0 >= 0 && x0 < W)         ? wx0 : 0.f;
    float vx1 = (x0 + 1 >= 0 && x0 + 1 < W) ? wx1 : 0.f;
    float vy0 = (y0 >= 0 && y0 < H)         ? wy0 : 0.f;
    float vy1 = (y0 + 1 >= 0 && y0 + 1 < H) ? wy1 : 0.f;

    __half2 hAB = __floats2half2_rn(a * vy0 * vx0, a * vy0 * vx1);
    __half2 hCD = __floats2half2_rn(a * vy1 * vx0, a * vy1 * vx1);
    uint32_t uAB = *reinterpret_cast<uint32_t*>(&hAB);
    uint32_t uCD = *reinterpret_cast<uint32_t*>(&hCD);

    int cx0 = min(max(x0, 0), W - 1);
    int cx1 = min(max(x0 + 1, 0), W - 1);
    int cy0 = min(max(y0, 0), H - 1);
    int cy1 = min(max(y0 + 1, 0), H - 1);

    int idxPack = (st + cy0 * W + cx0) * 16
                | ((cx1 - cx0) << 20)
                | ((cy1 - cy0) << 21);

    const __half2* vb2 = reinterpret_cast<const __half2*>(g_v_h)
                       + (size_t)(b * HEADS + h) * (NV * 16) + li;
    float accx = 0.f, accy = 0.f;
    const int srcbase = lane & 16;
    const int Wtab16[4] = {160 * 16, 80 * 16, 40 * 16, 20 * 16};

#pragma unroll
    for (int j = 0; j < 16; j++) {
        int src = srcbase + j;
        uint32_t pAB = __shfl_sync(0xffffffffu, uAB, src);
        uint32_t pCD = __shfl_sync(0xffffffffu, uCD, src);
        int      pk  = __shfl_sync(0xffffffffu, idxPack, src);

        int i00 = pk & 0xFFFFF;
        int dx  = ((pk >> 20) & 1) * 16;
        int dy  = ((pk >> 21) & 1) * Wtab16[j >> 2];

        float2 wab = __half22float2(*reinterpret_cast<const __half2*>(&pAB));
        float2 wcd = __half22float2(*reinterpret_cast<const __half2*>(&pCD));

        float2 f00 = __half22float2(vb2[i00]);
        float2 f10 = __half22float2(vb2[i00 + dx]);
        float2 f01 = __half22float2(vb2[i00 + dy]);
        float2 f11 = __half22float2(vb2[i00 + dx + dy]);

        accx += wab.x * f00.x + wab.y * f10.x + wcd.x * f01.x + wcd.y * f11.x;
        accy += wab.x * f00.y + wab.y * f10.y + wcd.x * f01.y + wcd.y * f11.y;
    }

    float2* outp = reinterpret_cast<float2*>(g_att + (size_t)bq * EMBED + h * DIM) + li;
    *outp = make_float2(accx, accy);
}

// ---------------------------------------------------------------------------
extern "C" void kernel_launch(void* const* d_in, const int* in_sizes, int n_in,
                              void* d_out, int out_size)
{
    (void)in_sizes; (void)n_in; (void)out_size;
    const float* query = (const float*)d_in[0];
    const float* value = (const float*)d_in[1];
    const float* qpos  = (const float*)d_in[2];
    const float* ref   = (const float*)d_in[3];
    const float* lro   = (const float*)d_in[4];
    const float* Wv    = (const float*)d_in[6];
    const float* bv    = (const float*)d_in[7];
    const float* Wo    = (const float*)d_in[8];
    const float* bo    = (const float*)d_in[9];
    const float* Wa    = (const float*)d_in[10];
    const float* ba    = (const float*)d_in[11];
    const float* Wout  = (const float*)d_in[12];
    const float* bout  = (const float*)d_in[13];
    float* out = (float*)d_out;

    // persistent streams + events (host objects only)
    static cudaStream_t sQ = nullptr, sS = nullptr;
    static cudaEvent_t  eFork = nullptr, eQo = nullptr, eDone = nullptr;
    static cudaEvent_t  evV[NCHUNK] = {nullptr, nullptr, nullptr, nullptr};
    if (!sQ) {
        cudaStreamCreateWithFlags(&sQ, cudaStreamNonBlocking);
        cudaStreamCreateWithFlags(&sS, cudaStreamNonBlocking);
        cudaEventCreateWithFlags(&eFork, cudaEventDisableTiming);
        cudaEventCreateWithFlags(&eQo,   cudaEventDisableTiming);
        cudaEventCreateWithFlags(&eDone, cudaEventDisableTiming);
        for (int c = 0; c < NCHUNK; c++)
            cudaEventCreateWithFlags(&evV[c], cudaEventDisableTiming);
    }

    // fork
    cudaEventRecord(eFork, 0);
    cudaStreamWaitEvent(sQ, eFork, 0);
    cudaStreamWaitEvent(sS, eFork, 0);

    // sQ: mode-1 GEMM (full) -> g_qo
    {
        dim3 g(3, (BS * NQ + 127) / 128);
        gemm_tc<1><<<g, 256, 0, sQ>>>(query, qpos, Wo, Wa, bo, ba, nullptr, nullptr,
                                      0, BS * NQ);
    }
    cudaEventRecord(eQo, sQ);
    cudaStreamWaitEvent(sS, eQo, 0);

    // main stream: conv + chunked value GEMM
    conv_wv<<<128, 256>>>(Wv);
    for (int c = 0; c < NCHUNK; c++) {
        int base = c * CH_ROWS_V;
        dim3 g(2, (CH_ROWS_V + 127) / 128);
        gemm_v_bf16<<<g, 256>>>(value, bv, base, base + CH_ROWS_V);
        cudaEventRecord(evV[c], 0);
        cudaStreamWaitEvent(sS, evV[c], 0);
        // sS: sampler + output GEMM for this chunk
        {
            int blocks = (CH_ROWS_Q * 4) / 8;   // 8 warps per block
            sample_kernel3<<<blocks, 256, 0, sS>>>(ref, lro, c * CH_ROWS_Q);
        }
        {
            int qbase = c * CH_ROWS_Q;
            dim3 g2(2, (CH_ROWS_Q + 127) / 128);
            gemm_tc<2><<<g2, 256, 0, sS>>>(nullptr, nullptr, Wout, nullptr, bout, nullptr,
                                           query, out, qbase, qbase + CH_ROWS_Q);
        }
    }
    cudaEventRecord(eDone, sS);
    cudaStreamWaitEvent(0, eDone, 0);
}

// round 15
// speedup vs baseline: 1.1548x; 1.1548x over previous
#include <cuda_runtime.h>
#include <cuda_fp16.h>
#include <cuda_bf16.h>
#include <math.h>
#include <stdint.h>

#define HEADS  8
#define LEVELS 4
#define POINTS 4
#define DIM    32
#define EMBED  256
#define NQ     1200
#define BS     8
#define NV     19560   // 92*160 + 46*80 + 23*40 + 12*20

#define OFF_N  256
#define QO_N   384

#define NCHUNK 2                    // batch chunks (4 batches each)
#define CH_ROWS_V (4 * NV)          // value rows per chunk (78240)
#define CH_ROWS_Q (4 * NQ)          // query rows per chunk (4800)

// Scratch (allocation-free rule: device globals)
__device__ __half    g_v_h[(size_t)BS * HEADS * NV * DIM]; // (b,h,pix,d) fp16 : 80 MB
__device__ float     g_qo[(size_t)BS * NQ * QO_N];         // offsets(256) || logits(128)
__device__ float     g_att[(size_t)BS * NQ * EMBED];
__device__ uint32_t  g_wvT[256 * 128];                     // Wv bf16 pairs [n][kk]

__constant__ int   c_H[4]    = {92, 46, 23, 12};
__constant__ int   c_W[4]    = {160, 80, 40, 20};
__constant__ int   c_start[4]= {0, 14720, 18400, 19320};
__constant__ float c_Hf[4]   = {92.f, 46.f, 23.f, 12.f};
__constant__ float c_Wf[4]   = {160.f, 80.f, 40.f, 20.f};
__constant__ float c_invH[4] = {1.f/92.f, 1.f/46.f, 1.f/23.f, 1.f/12.f};
__constant__ float c_invW[4] = {1.f/160.f, 1.f/80.f, 1.f/40.f, 1.f/20.f};

// ---------------------------------------------------------------------------
__global__ __launch_bounds__(256)
void conv_wv(const float* __restrict__ Wv)
{
    int idx = blockIdx.x * 256 + threadIdx.x;
    int n  = idx >> 7;
    int kk = idx & 127;
    float lo = Wv[(size_t)(2 * kk) * 256 + n];
    float hi = Wv[(size_t)(2 * kk + 1) * 256 + n];
    __nv_bfloat162 p = __floats2bfloat162_rn(lo, hi);
    g_wvT[n * 128 + kk] = *reinterpret_cast<uint32_t*>(&p);
}

// ===========================================================================
// bf16 mma.m16n8k16 value GEMM (R9 config + row-base param for chunking).
// ===========================================================================
__device__ __forceinline__ void mma_bf16(float& d0, float& d1, float& d2, float& d3,
                                         uint32_t a0, uint32_t a1, uint32_t a2, uint32_t a3,
                                         uint32_t b0, uint32_t b1) {
    asm volatile("mma.sync.aligned.m16n8k16.row.col.f32.bf16.bf16.f32 "
                 "{%0,%1,%2,%3},{%4,%5,%6,%7},{%8,%9},{%0,%1,%2,%3};"
                 : "+f"(d0), "+f"(d1), "+f"(d2), "+f"(d3)
                 : "r"(a0), "r"(a1), "r"(a2), "r"(a3), "r"(b0), "r"(b1));
}

__device__ __forceinline__ void ldsm_x4(uint32_t& r0, uint32_t& r1, uint32_t& r2, uint32_t& r3,
                                        uint32_t addr) {
    asm volatile("ldmatrix.sync.aligned.m8n8.x4.shared.b16 {%0,%1,%2,%3}, [%4];"
                 : "=r"(r0), "=r"(r1), "=r"(r2), "=r"(r3) : "r"(addr));
}

__device__ __forceinline__ uint32_t smem_u32(const void* p) {
    uint32_t a;
    asm("{ .reg .u64 t; cvta.to.shared.u64 t, %1; cvt.u32.u64 %0, t; }" : "=r"(a) : "l"(p));
    return a;
}

#define PSTRIDE 20
#define STG_ROW 40

__global__ __launch_bounds__(256)
void gemm_v_bf16(const float* __restrict__ A, const float* __restrict__ bias,
                 int base, int M)
{
    __shared__ uint32_t As[128][PSTRIDE];
    __shared__ uint32_t Bsm[128][PSTRIDE];

    const int tid  = threadIdx.x;
    const int lane = tid & 31;
    const int warp = tid >> 5;
    const int wm   = warp >> 2;
    const int wn   = warp & 3;
    const int tg   = lane >> 2;
    const int tig  = lane & 3;

    const int block_m = base + blockIdx.y * 128;
    const int block_n = blockIdx.x * 128;

    float acc[4][4][4];
#pragma unroll
    for (int i = 0; i < 4; i++)
#pragma unroll
        for (int j = 0; j < 4; j++)
#pragma unroll
            for (int r = 0; r < 4; r++) acc[i][j][r] = 0.f;

    float4 aS[4];
    uint4  bU[2];

    const int a_row0 = tid >> 3;
    const int a_c4   = (tid & 7) * 4;
    const int b_n    = tid >> 1;
    const int b_s0   = (tid & 1) * 2;

    uint32_t aAddr[4];
    {
        uint32_t bbase = smem_u32(As);
        int row = wm * 64 + (lane & 15);
        int po  = (lane >> 4) * 4;
#pragma unroll
        for (int mt = 0; mt < 4; mt++)
            aAddr[mt] = bbase + (uint32_t)(((row + mt * 16) * PSTRIDE + po) * 4);
    }
    uint32_t bAddr[2];
    {
        uint32_t bbase = smem_u32(Bsm);
        int row = wn * 32 + (lane & 7) + ((lane >> 4) & 1) * 8;
        int po  = ((lane >> 3) & 1) * 4;
#pragma unroll
        for (int g = 0; g < 2; g++)
            bAddr[g] = bbase + (uint32_t)(((row + g * 16) * PSTRIDE + po) * 4);
    }

    auto ldgA = [&](int k0) {
#pragma unroll
        for (int i = 0; i < 4; i++) {
            int gr = block_m + a_row0 + i * 32;
            float4 v = make_float4(0.f, 0.f, 0.f, 0.f);
            if (gr < M)
                v = *reinterpret_cast<const float4*>(A + (size_t)gr * 256 + k0 + a_c4);
            aS[i] = v;
        }
    };
    auto ldgB = [&](int k0) {
        int kk0 = k0 >> 1;
#pragma unroll
        for (int j = 0; j < 2; j++)
            bU[j] = *reinterpret_cast<const uint4*>(
                &g_wvT[(block_n + b_n) * 128 + kk0 + (b_s0 + j) * 4]);
    };
    auto sts = [&]() {
#pragma unroll
        for (int i = 0; i < 4; i++) {
            __nv_bfloat162 p0 = __floats2bfloat162_rn(aS[i].x, aS[i].y);
            __nv_bfloat162 p1 = __floats2bfloat162_rn(aS[i].z, aS[i].w);
            uint2 u;
            u.x = *reinterpret_cast<uint32_t*>(&p0);
            u.y = *reinterpret_cast<uint32_t*>(&p1);
            *reinterpret_cast<uint2*>(&As[a_row0 + i * 32][(a_c4 >> 1)]) = u;
        }
#pragma unroll
        for (int j = 0; j < 2; j++)
            *reinterpret_cast<uint4*>(&Bsm[b_n][(b_s0 + j) * 4]) = bU[j];
    };

    ldgA(0); ldgB(0);

    for (int k0 = 0; k0 < 256; k0 += 32) {
        sts();
        __syncthreads();
        if (k0 + 32 < 256) { ldgA(k0 + 32); ldgB(k0 + 32); }

#pragma unroll
        for (int s = 0; s < 2; s++) {
            const uint32_t soff = (uint32_t)(s * 32);
            uint32_t a[4][4], b[4][2];
#pragma unroll
            for (int mt = 0; mt < 4; mt++)
                ldsm_x4(a[mt][0], a[mt][1], a[mt][2], a[mt][3], aAddr[mt] + soff);
#pragma unroll
            for (int g = 0; g < 2; g++)
                ldsm_x4(b[2 * g][0], b[2 * g][1], b[2 * g + 1][0], b[2 * g + 1][1],
                        bAddr[g] + soff);
#pragma unroll
            for (int mt = 0; mt < 4; mt++)
#pragma unroll
                for (int nt = 0; nt < 4; nt++)
                    mma_bf16(acc[mt][nt][0], acc[mt][nt][1], acc[mt][nt][2], acc[mt][nt][3],
                             a[mt][0], a[mt][1], a[mt][2], a[mt][3],
                             b[nt][0], b[nt][1]);
        }
        __syncthreads();
    }

    // coalesced epilogue
    const int head = 4 * blockIdx.x + wn;
    __half* stg = reinterpret_cast<__half*>(As) + warp * (16 * STG_ROW);
    const float bx[4] = { bias[head * 32 + 0 * 8 + 2 * tig], bias[head * 32 + 1 * 8 + 2 * tig],
                          bias[head * 32 + 2 * 8 + 2 * tig], bias[head * 32 + 3 * 8 + 2 * tig] };
    const float by[4] = { bias[head * 32 + 0 * 8 + 2 * tig + 1], bias[head * 32 + 1 * 8 + 2 * tig + 1],
                          bias[head * 32 + 2 * 8 + 2 * tig + 1], bias[head * 32 + 3 * 8 + 2 * tig + 1] };

#pragma unroll
    for (int mt = 0; mt < 4; mt++) {
#pragma unroll
        for (int nt = 0; nt < 4; nt++) {
#pragma unroll
            for (int rr = 0; rr < 2; rr++) {
                int r = tg + rr * 8;
                __half2 v = __floats2half2_rn(acc[mt][nt][rr * 2 + 0] + bx[nt],
                                              acc[mt][nt][rr * 2 + 1] + by[nt]);
                *reinterpret_cast<__half2*>(&stg[r * STG_ROW + nt * 8 + 2 * tig]) = v;
            }
        }
        __syncwarp();
#pragma unroll
        for (int pass = 0; pass < 2; pass++) {
            int t    = pass * 32 + lane;
            int row  = t >> 2;
            int c16  = (t & 3) * 8;
            int pixr = block_m + wm * 64 + mt * 16 + row;
            if (pixr < M) {
                int b = pixr / NV;
                int n = pixr - b * NV;
                uint4 v = *reinterpret_cast<const uint4*>(&stg[row * STG_ROW + c16]);
                *reinterpret_cast<uint4*>(
                    g_v_h + ((size_t)(b * HEADS + head) * NV + n) * DIM + c16) = v;
            }
        }
        __syncwarp();
    }
}

// ===========================================================================
// tf32 mma.sync GEMM for modes 1,2 (+ row-base param).
// ===========================================================================
__device__ __forceinline__ uint32_t f2tf32(float f) {
    uint32_t u;
    asm("cvt.rna.tf32.f32 %0, %1;" : "=r"(u) : "f"(f));
    return u;
}

__device__ __forceinline__ void mma_tf32(float& d0, float& d1, float& d2, float& d3,
                                         uint32_t a0, uint32_t a1, uint32_t a2, uint32_t a3,
                                         uint32_t b0, uint32_t b1) {
    asm volatile("mma.sync.aligned.m16n8k8.row.col.f32.tf32.tf32.f32 "
                 "{%0,%1,%2,%3},{%4,%5,%6,%7},{%8,%9},{%0,%1,%2,%3};"
                 : "+f"(d0), "+f"(d1), "+f"(d2), "+f"(d3)
                 : "r"(a0), "r"(a1), "r"(a2), "r"(a3), "r"(b0), "r"(b1));
}

#define AS_STRIDE 36
#define BS_STRIDE 136

template <int MODE>
__global__ __launch_bounds__(256)
void gemm_tc(const float* __restrict__ Aext, const float* __restrict__ A2,
             const float* __restrict__ B1,  const float* __restrict__ B2,
             const float* __restrict__ bias1, const float* __restrict__ bias2,
             const float* __restrict__ addsrc, float* __restrict__ Cext,
             int base, int M)
{
    __shared__ uint32_t As[128][AS_STRIDE];
    __shared__ uint32_t Bsm[32][BS_STRIDE];

    const float* A = (MODE == 2) ? g_att : Aext;

    const int tid  = threadIdx.x;
    const int lane = tid & 31;
    const int warp = tid >> 5;
    const int wm   = warp >> 2;
    const int wn   = warp & 3;
    const int tg   = lane >> 2;
    const int tig  = lane & 3;

    const int block_m = base + blockIdx.y * 128;
    const int block_n = blockIdx.x * 128;

    float acc[4][4][4];
#pragma unroll
    for (int i = 0; i < 4; i++)
#pragma unroll
        for (int j = 0; j < 4; j++)
#pragma unroll
            for (int r = 0; r < 4; r++) acc[i][j][r] = 0.f;

    float4 aS[4], bS[4];
    const int a_row0 = tid >> 3;
    const int a_c4   = (tid & 7) * 4;
    const int b_k0   = tid >> 5;
    const int b_n4   = lane * 4;

    auto ldgA = [&](int k0) {
#pragma unroll
        for (int i = 0; i < 4; i++) {
            int gr = block_m + a_row0 + i * 32;
            float4 v = make_float4(0.f, 0.f, 0.f, 0.f);
            if (gr < M) {
                v = *reinterpret_cast<const float4*>(A + (size_t)gr * 256 + k0 + a_c4);
                if (MODE == 1) {
                    float4 v2 = *reinterpret_cast<const float4*>(A2 + (size_t)gr * 256 + k0 + a_c4);
                    v.x += v2.x; v.y += v2.y; v.z += v2.z; v.w += v2.w;
                }
            }
            aS[i] = v;
        }
    };
    auto ldgB = [&](int k0) {
#pragma unroll
        for (int i = 0; i < 4; i++) {
            int krow = b_k0 + i * 8;
            int gc   = block_n + b_n4;
            float4 v;
            if (MODE == 1) {
                if (gc < OFF_N) v = *reinterpret_cast<const float4*>(B1 + (size_t)(k0 + krow) * OFF_N + gc);
                else            v = *reinterpret_cast<const float4*>(B2 + (size_t)(k0 + krow) * 128 + (gc - OFF_N));
            } else {
                v = *reinterpret_cast<const float4*>(B1 + (size_t)(k0 + krow) * 256 + gc);
            }
            bS[i] = v;
        }
    };
    auto sts = [&]() {
#pragma unroll
        for (int i = 0; i < 4; i++) {
            uint4 u;
            u.x = f2tf32(aS[i].x); u.y = f2tf32(aS[i].y);
            u.z = f2tf32(aS[i].z); u.w = f2tf32(aS[i].w);
            *reinterpret_cast<uint4*>(&As[a_row0 + i * 32][a_c4]) = u;
        }
#pragma unroll
        for (int i = 0; i < 4; i++) {
            uint4 u;
            u.x = f2tf32(bS[i].x); u.y = f2tf32(bS[i].y);
            u.z = f2tf32(bS[i].z); u.w = f2tf32(bS[i].w);
            *reinterpret_cast<uint4*>(&Bsm[b_k0 + i * 8][b_n4]) = u;
        }
    };

    ldgA(0); ldgB(0);

    for (int k0 = 0; k0 < 256; k0 += 32) {
        sts();
        __syncthreads();
        if (k0 + 32 < 256) { ldgA(k0 + 32); ldgB(k0 + 32); }

#pragma unroll
        for (int ks = 0; ks < 4; ks++) {
            const int k = ks * 8;
            uint32_t a[4][4], b[4][2];
#pragma unroll
            for (int mt = 0; mt < 4; mt++) {
                int m = wm * 64 + mt * 16 + tg;
                a[mt][0] = As[m][k + tig];
                a[mt][1] = As[m + 8][k + tig];
                a[mt][2] = As[m][k + tig + 4];
                a[mt][3] = As[m + 8][k + tig + 4];
            }
#pragma unroll
            for (int nt = 0; nt < 4; nt++) {
                int n = wn * 32 + nt * 8 + tg;
                b[nt][0] = Bsm[k + tig][n];
                b[nt][1] = Bsm[k + tig + 4][n];
            }
#pragma unroll
            for (int mt = 0; mt < 4; mt++)
#pragma unroll
                for (int nt = 0; nt < 4; nt++)
                    mma_tf32(acc[mt][nt][0], acc[mt][nt][1], acc[mt][nt][2], acc[mt][nt][3],
                             a[mt][0], a[mt][1], a[mt][2], a[mt][3],
                             b[nt][0], b[nt][1]);
        }
        __syncthreads();
    }

#pragma unroll
    for (int mt = 0; mt < 4; mt++) {
#pragma unroll
        for (int nt = 0; nt < 4; nt++) {
            int gc = block_n + wn * 32 + nt * 8 + 2 * tig;
            float bx, by;
            if (MODE == 1) {
                bx = (gc < OFF_N) ? bias1[gc] : bias2[gc - OFF_N];
                by = (gc + 1 < OFF_N) ? bias1[gc + 1] : bias2[gc + 1 - OFF_N];
            } else {
                bx = bias1[gc]; by = bias1[gc + 1];
            }
#pragma unroll
            for (int rr = 0; rr < 2; rr++) {
                int gr = block_m + wm * 64 + mt * 16 + tg + rr * 8;
                if (gr >= M) continue;
                float ox = acc[mt][nt][rr * 2 + 0] + bx;
                float oy = acc[mt][nt][rr * 2 + 1] + by;
                if (MODE == 1) {
                    float2 o; o.x = ox; o.y = oy;
                    *reinterpret_cast<float2*>(g_qo + (size_t)gr * QO_N + gc) = o;
                } else {
                    const float2 idv = *reinterpret_cast<const float2*>(addsrc + (size_t)gr * 256 + gc);
                    float2 o; o.x = ox + idv.x; o.y = oy + idv.y;
                    *reinterpret_cast<float2*>(Cext + (size_t)gr * 256 + gc) = o;
                }
            }
        }
    }
}

// ===========================================================================
// Sampling v3 (+ bq-base param for chunking).
// ===========================================================================
__global__ __launch_bounds__(256)
void sample_kernel3(const float* __restrict__ ref, const float* __restrict__ lro,
                    int bqBase)
{
    int gwarp = (blockIdx.x * blockDim.x + threadIdx.x) >> 5;
    int lane  = threadIdx.x & 31;
    int hp    = gwarp & 3;
    int bq    = bqBase + (gwarp >> 2);
    int b  = bq / NQ;
    int hi = lane >> 4;
    int li = lane & 15;
    int h  = hp * 2 + hi;

    const float* row = g_qo + (size_t)bq * QO_N;

    float logit = row[OFF_N + h * 16 + li];
    float m = logit;
#pragma unroll
    for (int s = 8; s; s >>= 1) m = fmaxf(m, __shfl_xor_sync(0xffffffffu, m, s));
    float e = expf(logit - m);
    float ss = e;
#pragma unroll
    for (int s = 8; s; s >>= 1) ss += __shfl_xor_sync(0xffffffffu, ss, s);
    float a = e / ss;

    int l = li >> 2;
    int p = li & 3;
    int W = c_W[l], H = c_H[l], st = c_start[l];

    float rx = ref[(size_t)(bq * 4 + l) * 2 + 0];
    float ry = ref[(size_t)(bq * 4 + l) * 2 + 1];
    float lx = lro[(size_t)(bq * 8 + h) * 2 + 0];
    float ly = lro[(size_t)(bq * 8 + h) * 2 + 1];
    float ox = row[((h * 4 + l) * 4 + p) * 2 + 0];
    float oy = row[((h * 4 + l) * 4 + p) * 2 + 1];

    float px = (rx + ox * c_invW[l] + lx) * c_Wf[l] - 0.5f;
    float py = (ry + oy * c_invH[l] + ly) * c_Hf[l] - 0.5f;

    float x0f = floorf(px), y0f = floorf(py);
    int   x0  = (int)x0f,   y0  = (int)y0f;
    float wx1 = px - x0f, wx0 = 1.f - wx1;
    float wy1 = py - y0f, wy0 = 1.f - wy1;

    float vx0 = (x0 >= 0 && x0 < W)         ? wx0 : 0.f;
    float vx1 = (x0 + 1 >= 0 && x0 + 1 < W) ? wx1 : 0.f;
    float vy0 = (y0 >= 0 && y0 < H)         ? wy0 : 0.f;
    float vy1 = (y0 + 1 >= 0 && y0 + 1 < H) ? wy1 : 0.f;

    __half2 hAB = __floats2half2_rn(a * vy0 * vx0, a * vy0 * vx1);
    __half2 hCD = __floats2half2_rn(a * vy1 * vx0, a * vy1 * vx1);
    uint32_t uAB = *reinterpret_cast<uint32_t*>(&hAB);
    uint32_t uCD = *reinterpret_cast<uint32_t*>(&hCD);

    int cx0 = min(max(x0, 0), W - 1);
    int cx1 = min(max(x0 + 1, 0), W - 1);
    int cy0 = min(max(y0, 0), H - 1);
    int cy1 = min(max(y0 + 1, 0), H - 1);

    int idxPack = (st + cy0 * W + cx0) * 16
                | ((cx1 - cx0) << 20)
                | ((cy1 - cy0) << 21);

    const __half2* vb2 = reinterpret_cast<const __half2*>(g_v_h)
                       + (size_t)(b * HEADS + h) * (NV * 16) + li;
    float accx = 0.f, accy = 0.f;
    const int srcbase = lane & 16;
    const int Wtab16[4] = {160 * 16, 80 * 16, 40 * 16, 20 * 16};

#pragma unroll
    for (int j = 0; j < 16; j++) {
        int src = srcbase + j;
        uint32_t pAB = __shfl_sync(0xffffffffu, uAB, src);
        uint32_t pCD = __shfl_sync(0xffffffffu, uCD, src);
        int      pk  = __shfl_sync(0xffffffffu, idxPack, src);

        int i00 = pk & 0xFFFFF;
        int dx  = ((pk >> 20) & 1) * 16;
        int dy  = ((pk >> 21) & 1) * Wtab16[j >> 2];

        float2 wab = __half22float2(*reinterpret_cast<const __half2*>(&pAB));
        float2 wcd = __half22float2(*reinterpret_cast<const __half2*>(&pCD));

        float2 f00 = __half22float2(vb2[i00]);
        float2 f10 = __half22float2(vb2[i00 + dx]);
        float2 f01 = __half22float2(vb2[i00 + dy]);
        float2 f11 = __half22float2(vb2[i00 + dx + dy]);

        accx += wab.x * f00.x + wab.y * f10.x + wcd.x * f01.x + wcd.y * f11.x;
        accy += wab.x * f00.y + wab.y * f10.y + wcd.x * f01.y + wcd.y * f11.y;
    }

    float2* outp = reinterpret_cast<float2*>(g_att + (size_t)bq * EMBED + h * DIM) + li;
    *outp = make_float2(accx, accy);
}

// ---------------------------------------------------------------------------
extern "C" void kernel_launch(void* const* d_in, const int* in_sizes, int n_in,
                              void* d_out, int out_size)
{
    (void)in_sizes; (void)n_in; (void)out_size;
    const float* query = (const float*)d_in[0];
    const float* value = (const float*)d_in[1];
    const float* qpos  = (const float*)d_in[2];
    const float* ref   = (const float*)d_in[3];
    const float* lro   = (const float*)d_in[4];
    const float* Wv    = (const float*)d_in[6];
    const float* bv    = (const float*)d_in[7];
    const float* Wo    = (const float*)d_in[8];
    const float* bo    = (const float*)d_in[9];
    const float* Wa    = (const float*)d_in[10];
    const float* ba    = (const float*)d_in[11];
    const float* Wout  = (const float*)d_in[12];
    const float* bout  = (const float*)d_in[13];
    float* out = (float*)d_out;

    // persistent streams + events (host objects only)
    static cudaStream_t sQ = nullptr, sS = nullptr;
    static cudaEvent_t  eFork = nullptr, eQo = nullptr, eDone = nullptr;
    static cudaEvent_t  evV[NCHUNK] = {nullptr, nullptr};
    if (!sQ) {
        cudaStreamCreateWithFlags(&sQ, cudaStreamNonBlocking);
        cudaStreamCreateWithFlags(&sS, cudaStreamNonBlocking);
        cudaEventCreateWithFlags(&eFork, cudaEventDisableTiming);
        cudaEventCreateWithFlags(&eQo,   cudaEventDisableTiming);
        cudaEventCreateWithFlags(&eDone, cudaEventDisableTiming);
        for (int c = 0; c < NCHUNK; c++)
            cudaEventCreateWithFlags(&evV[c], cudaEventDisableTiming);
    }

    // fork
    cudaEventRecord(eFork, 0);
    cudaStreamWaitEvent(sQ, eFork, 0);
    cudaStreamWaitEvent(sS, eFork, 0);

    // sQ: mode-1 GEMM (full) -> g_qo
    {
        dim3 g(3, (BS * NQ + 127) / 128);
        gemm_tc<1><<<g, 256, 0, sQ>>>(query, qpos, Wo, Wa, bo, ba, nullptr, nullptr,
                                      0, BS * NQ);
    }
    cudaEventRecord(eQo, sQ);
    cudaStreamWaitEvent(sS, eQo, 0);

    // main stream: conv + 2-chunk value GEMM
    conv_wv<<<128, 256>>>(Wv);
    for (int c = 0; c < NCHUNK; c++) {
        int base = c * CH_ROWS_V;
        dim3 g(2, (CH_ROWS_V + 127) / 128);
        gemm_v_bf16<<<g, 256>>>(value, bv, base, base + CH_ROWS_V);
        cudaEventRecord(evV[c], 0);
        cudaStreamWaitEvent(sS, evV[c], 0);
        // sS: sampler + output GEMM for this chunk
        {
            int blocks = (CH_ROWS_Q * 4) / 8;   // 8 warps per block
            sample_kernel3<<<blocks, 256, 0, sS>>>(ref, lro, c * CH_ROWS_Q);
        }
        {
            int qbase = c * CH_ROWS_Q;
            dim3 g2(2, (CH_ROWS_Q + 127) / 128);
            gemm_tc<2><<<g2, 256, 0, sS>>>(nullptr, nullptr, Wout, nullptr, bout, nullptr,
                                           query, out, qbase, qbase + CH_ROWS_Q);
        }
    }
    cudaEventRecord(eDone, sS);
    cudaStreamWaitEvent(0, eDone, 0);
}

// round 16
// speedup vs baseline: 1.2815x; 1.1097x over previous
#include <cuda_runtime.h>
#include <cuda_fp16.h>
#include <cuda_bf16.h>
#include <math.h>
#include <stdint.h>

#define HEADS  8
#define LEVELS 4
#define POINTS 4
#define DIM    32
#define EMBED  256
#define NQ     1200
#define BS     8
#define NV     19560   // 92*160 + 46*80 + 23*40 + 12*20

#define OFF_N  256
#define QO_N   384

// Scratch (allocation-free rule: device globals)
__device__ __half    g_v_h[(size_t)BS * HEADS * NV * DIM]; // (b,h,pix,d) fp16 : 80 MB
__device__ float     g_qo[(size_t)BS * NQ * QO_N];         // offsets(256) || logits(128)
__device__ float     g_att[(size_t)BS * NQ * EMBED];
__device__ uint32_t  g_wvT[256 * 128];                     // Wv bf16 pairs [n][kk]

__constant__ int   c_H[4]    = {92, 46, 23, 12};
__constant__ int   c_W[4]    = {160, 80, 40, 20};
__constant__ int   c_start[4]= {0, 14720, 18400, 19320};
__constant__ float c_Hf[4]   = {92.f, 46.f, 23.f, 12.f};
__constant__ float c_Wf[4]   = {160.f, 80.f, 40.f, 20.f};
__constant__ float c_invH[4] = {1.f/92.f, 1.f/46.f, 1.f/23.f, 1.f/12.f};
__constant__ float c_invW[4] = {1.f/160.f, 1.f/80.f, 1.f/40.f, 1.f/20.f};

// ---------------------------------------------------------------------------
__global__ __launch_bounds__(256)
void conv_wv(const float* __restrict__ Wv)
{
    int idx = blockIdx.x * 256 + threadIdx.x;
    int n  = idx >> 7;
    int kk = idx & 127;
    float lo = Wv[(size_t)(2 * kk) * 256 + n];
    float hi = Wv[(size_t)(2 * kk + 1) * 256 + n];
    __nv_bfloat162 p = __floats2bfloat162_rn(lo, hi);
    g_wvT[n * 128 + kk] = *reinterpret_cast<uint32_t*>(&p);
}

// ===========================================================================
// bf16 mma.m16n8k16 value GEMM (R9 config). A loads use __ldcs (evict-first:
// single-use stream) so g_v_h writes stay L2-resident for the sampler.
// ===========================================================================
__device__ __forceinline__ void mma_bf16(float& d0, float& d1, float& d2, float& d3,
                                         uint32_t a0, uint32_t a1, uint32_t a2, uint32_t a3,
                                         uint32_t b0, uint32_t b1) {
    asm volatile("mma.sync.aligned.m16n8k16.row.col.f32.bf16.bf16.f32 "
                 "{%0,%1,%2,%3},{%4,%5,%6,%7},{%8,%9},{%0,%1,%2,%3};"
                 : "+f"(d0), "+f"(d1), "+f"(d2), "+f"(d3)
                 : "r"(a0), "r"(a1), "r"(a2), "r"(a3), "r"(b0), "r"(b1));
}

__device__ __forceinline__ void ldsm_x4(uint32_t& r0, uint32_t& r1, uint32_t& r2, uint32_t& r3,
                                        uint32_t addr) {
    asm volatile("ldmatrix.sync.aligned.m8n8.x4.shared.b16 {%0,%1,%2,%3}, [%4];"
                 : "=r"(r0), "=r"(r1), "=r"(r2), "=r"(r3) : "r"(addr));
}

__device__ __forceinline__ uint32_t smem_u32(const void* p) {
    uint32_t a;
    asm("{ .reg .u64 t; cvta.to.shared.u64 t, %1; cvt.u32.u64 %0, t; }" : "=r"(a) : "l"(p));
    return a;
}

#define PSTRIDE 20   // 16 kpairs + 4 pad (uint32)
#define STG_ROW 40   // staging row stride in halves

__global__ __launch_bounds__(256)
void gemm_v_bf16(const float* __restrict__ A, const float* __restrict__ bias, int M)
{
    __shared__ uint32_t As[128][PSTRIDE];   // [m][kpair]; reused as epilogue staging
    __shared__ uint32_t Bsm[128][PSTRIDE];  // [n][kpair]

    const int tid  = threadIdx.x;
    const int lane = tid & 31;
    const int warp = tid >> 5;
    const int wm   = warp >> 2;
    const int wn   = warp & 3;
    const int tg   = lane >> 2;
    const int tig  = lane & 3;

    const int block_m = blockIdx.y * 128;
    const int block_n = blockIdx.x * 128;

    float acc[4][4][4];
#pragma unroll
    for (int i = 0; i < 4; i++)
#pragma unroll
        for (int j = 0; j < 4; j++)
#pragma unroll
            for (int r = 0; r < 4; r++) acc[i][j][r] = 0.f;

    float4 aS[4];
    uint4  bU[2];

    const int a_row0 = tid >> 3;
    const int a_c4   = (tid & 7) * 4;
    const int b_n    = tid >> 1;
    const int b_s0   = (tid & 1) * 2;

    uint32_t aAddr[4];
    {
        uint32_t base = smem_u32(As);
        int row = wm * 64 + (lane & 15);
        int po  = (lane >> 4) * 4;
#pragma unroll
        for (int mt = 0; mt < 4; mt++)
            aAddr[mt] = base + (uint32_t)(((row + mt * 16) * PSTRIDE + po) * 4);
    }
    uint32_t bAddr[2];
    {
        uint32_t base = smem_u32(Bsm);
        int row = wn * 32 + (lane & 7) + ((lane >> 4) & 1) * 8;
        int po  = ((lane >> 3) & 1) * 4;
#pragma unroll
        for (int g = 0; g < 2; g++)
            bAddr[g] = base + (uint32_t)(((row + g * 16) * PSTRIDE + po) * 4);
    }

    auto ldgA = [&](int k0) {
#pragma unroll
        for (int i = 0; i < 4; i++) {
            int gr = block_m + a_row0 + i * 32;
            float4 v = make_float4(0.f, 0.f, 0.f, 0.f);
            if (gr < M)
                v = __ldcs(reinterpret_cast<const float4*>(A + (size_t)gr * 256 + k0 + a_c4));
            aS[i] = v;
        }
    };
    auto ldgB = [&](int k0) {
        int kk0 = k0 >> 1;
#pragma unroll
        for (int j = 0; j < 2; j++)
            bU[j] = *reinterpret_cast<const uint4*>(
                &g_wvT[(block_n + b_n) * 128 + kk0 + (b_s0 + j) * 4]);
    };
    auto sts = [&]() {
#pragma unroll
        for (int i = 0; i < 4; i++) {
            __nv_bfloat162 p0 = __floats2bfloat162_rn(aS[i].x, aS[i].y);
            __nv_bfloat162 p1 = __floats2bfloat162_rn(aS[i].z, aS[i].w);
            uint2 u;
            u.x = *reinterpret_cast<uint32_t*>(&p0);
            u.y = *reinterpret_cast<uint32_t*>(&p1);
            *reinterpret_cast<uint2*>(&As[a_row0 + i * 32][(a_c4 >> 1)]) = u;
        }
#pragma unroll
        for (int j = 0; j < 2; j++)
            *reinterpret_cast<uint4*>(&Bsm[b_n][(b_s0 + j) * 4]) = bU[j];
    };

    ldgA(0); ldgB(0);

    for (int k0 = 0; k0 < 256; k0 += 32) {
        sts();
        __syncthreads();
        if (k0 + 32 < 256) { ldgA(k0 + 32); ldgB(k0 + 32); }

#pragma unroll
        for (int s = 0; s < 2; s++) {
            const uint32_t soff = (uint32_t)(s * 32);
            uint32_t a[4][4], b[4][2];
#pragma unroll
            for (int mt = 0; mt < 4; mt++)
                ldsm_x4(a[mt][0], a[mt][1], a[mt][2], a[mt][3], aAddr[mt] + soff);
#pragma unroll
            for (int g = 0; g < 2; g++)
                ldsm_x4(b[2 * g][0], b[2 * g][1], b[2 * g + 1][0], b[2 * g + 1][1],
                        bAddr[g] + soff);
#pragma unroll
            for (int mt = 0; mt < 4; mt++)
#pragma unroll
                for (int nt = 0; nt < 4; nt++)
                    mma_bf16(acc[mt][nt][0], acc[mt][nt][1], acc[mt][nt][2], acc[mt][nt][3],
                             a[mt][0], a[mt][1], a[mt][2], a[mt][3],
                             b[nt][0], b[nt][1]);
        }
        __syncthreads();
    }

    // ===== coalesced epilogue =====
    const int head = 4 * blockIdx.x + wn;
    __half* stg = reinterpret_cast<__half*>(As) + warp * (16 * STG_ROW);
    const float bx[4] = { bias[head * 32 + 0 * 8 + 2 * tig], bias[head * 32 + 1 * 8 + 2 * tig],
                          bias[head * 32 + 2 * 8 + 2 * tig], bias[head * 32 + 3 * 8 + 2 * tig] };
    const float by[4] = { bias[head * 32 + 0 * 8 + 2 * tig + 1], bias[head * 32 + 1 * 8 + 2 * tig + 1],
                          bias[head * 32 + 2 * 8 + 2 * tig + 1], bias[head * 32 + 3 * 8 + 2 * tig + 1] };

#pragma unroll
    for (int mt = 0; mt < 4; mt++) {
#pragma unroll
        for (int nt = 0; nt < 4; nt++) {
#pragma unroll
            for (int rr = 0; rr < 2; rr++) {
                int r = tg + rr * 8;
                __half2 v = __floats2half2_rn(acc[mt][nt][rr * 2 + 0] + bx[nt],
                                              acc[mt][nt][rr * 2 + 1] + by[nt]);
                *reinterpret_cast<__half2*>(&stg[r * STG_ROW + nt * 8 + 2 * tig]) = v;
            }
        }
        __syncwarp();
#pragma unroll
        for (int pass = 0; pass < 2; pass++) {
            int t    = pass * 32 + lane;
            int row  = t >> 2;
            int c16  = (t & 3) * 8;
            int pixr = block_m + wm * 64 + mt * 16 + row;
            if (pixr < M) {
                int b = pixr / NV;
                int n = pixr - b * NV;
                uint4 v = *reinterpret_cast<const uint4*>(&stg[row * STG_ROW + c16]);
                *reinterpret_cast<uint4*>(
                    g_v_h + ((size_t)(b * HEADS + head) * NV + n) * DIM + c16) = v;
            }
        }
        __syncwarp();
    }
}

// ===========================================================================
// tf32 mma.sync GEMM for modes 1,2 (unchanged from R13).
// ===========================================================================
__device__ __forceinline__ uint32_t f2tf32(float f) {
    uint32_t u;
    asm("cvt.rna.tf32.f32 %0, %1;" : "=r"(u) : "f"(f));
    return u;
}

__device__ __forceinline__ void mma_tf32(float& d0, float& d1, float& d2, float& d3,
                                         uint32_t a0, uint32_t a1, uint32_t a2, uint32_t a3,
                                         uint32_t b0, uint32_t b1) {
    asm volatile("mma.sync.aligned.m16n8k8.row.col.f32.tf32.tf32.f32 "
                 "{%0,%1,%2,%3},{%4,%5,%6,%7},{%8,%9},{%0,%1,%2,%3};"
                 : "+f"(d0), "+f"(d1), "+f"(d2), "+f"(d3)
                 : "r"(a0), "r"(a1), "r"(a2), "r"(a3), "r"(b0), "r"(b1));
}

#define AS_STRIDE 36
#define BS_STRIDE 136

template <int MODE>
__global__ __launch_bounds__(256)
void gemm_tc(const float* __restrict__ Aext, const float* __restrict__ A2,
             const float* __restrict__ B1,  const float* __restrict__ B2,
             const float* __restrict__ bias1, const float* __restrict__ bias2,
             const float* __restrict__ addsrc, float* __restrict__ Cext, int M)
{
    __shared__ uint32_t As[128][AS_STRIDE];
    __shared__ uint32_t Bsm[32][BS_STRIDE];

    const float* A = (MODE == 2) ? g_att : Aext;

    const int tid  = threadIdx.x;
    const int lane = tid & 31;
    const int warp = tid >> 5;
    const int wm   = warp >> 2;
    const int wn   = warp & 3;
    const int tg   = lane >> 2;
    const int tig  = lane & 3;

    const int block_m = blockIdx.y * 128;
    const int block_n = blockIdx.x * 128;

    float acc[4][4][4];
#pragma unroll
    for (int i = 0; i < 4; i++)
#pragma unroll
        for (int j = 0; j < 4; j++)
#pragma unroll
            for (int r = 0; r < 4; r++) acc[i][j][r] = 0.f;

    float4 aS[4], bS[4];
    const int a_row0 = tid >> 3;
    const int a_c4   = (tid & 7) * 4;
    const int b_k0   = tid >> 5;
    const int b_n4   = lane * 4;

    auto ldgA = [&](int k0) {
#pragma unroll
        for (int i = 0; i < 4; i++) {
            int gr = block_m + a_row0 + i * 32;
            float4 v = make_float4(0.f, 0.f, 0.f, 0.f);
            if (gr < M) {
                v = *reinterpret_cast<const float4*>(A + (size_t)gr * 256 + k0 + a_c4);
                if (MODE == 1) {
                    float4 v2 = *reinterpret_cast<const float4*>(A2 + (size_t)gr * 256 + k0 + a_c4);
                    v.x += v2.x; v.y += v2.y; v.z += v2.z; v.w += v2.w;
                }
            }
            aS[i] = v;
        }
    };
    auto ldgB = [&](int k0) {
#pragma unroll
        for (int i = 0; i < 4; i++) {
            int krow = b_k0 + i * 8;
            int gc   = block_n + b_n4;
            float4 v;
            if (MODE == 1) {
                if (gc < OFF_N) v = *reinterpret_cast<const float4*>(B1 + (size_t)(k0 + krow) * OFF_N + gc);
                else            v = *reinterpret_cast<const float4*>(B2 + (size_t)(k0 + krow) * 128 + (gc - OFF_N));
            } else {
                v = *reinterpret_cast<const float4*>(B1 + (size_t)(k0 + krow) * 256 + gc);
            }
            bS[i] = v;
        }
    };
    auto sts = [&]() {
#pragma unroll
        for (int i = 0; i < 4; i++) {
            uint4 u;
            u.x = f2tf32(aS[i].x); u.y = f2tf32(aS[i].y);
            u.z = f2tf32(aS[i].z); u.w = f2tf32(aS[i].w);
            *reinterpret_cast<uint4*>(&As[a_row0 + i * 32][a_c4]) = u;
        }
#pragma unroll
        for (int i = 0; i < 4; i++) {
            uint4 u;
            u.x = f2tf32(bS[i].x); u.y = f2tf32(bS[i].y);
            u.z = f2tf32(bS[i].z); u.w = f2tf32(bS[i].w);
            *reinterpret_cast<uint4*>(&Bsm[b_k0 + i * 8][b_n4]) = u;
        }
    };

    ldgA(0); ldgB(0);

    for (int k0 = 0; k0 < 256; k0 += 32) {
        sts();
        __syncthreads();
        if (k0 + 32 < 256) { ldgA(k0 + 32); ldgB(k0 + 32); }

#pragma unroll
        for (int ks = 0; ks < 4; ks++) {
            const int k = ks * 8;
            uint32_t a[4][4], b[4][2];
#pragma unroll
            for (int mt = 0; mt < 4; mt++) {
                int m = wm * 64 + mt * 16 + tg;
                a[mt][0] = As[m][k + tig];
                a[mt][1] = As[m + 8][k + tig];
                a[mt][2] = As[m][k + tig + 4];
                a[mt][3] = As[m + 8][k + tig + 4];
            }
#pragma unroll
            for (int nt = 0; nt < 4; nt++) {
                int n = wn * 32 + nt * 8 + tg;
                b[nt][0] = Bsm[k + tig][n];
                b[nt][1] = Bsm[k + tig + 4][n];
            }
#pragma unroll
            for (int mt = 0; mt < 4; mt++)
#pragma unroll
                for (int nt = 0; nt < 4; nt++)
                    mma_tf32(acc[mt][nt][0], acc[mt][nt][1], acc[mt][nt][2], acc[mt][nt][3],
                             a[mt][0], a[mt][1], a[mt][2], a[mt][3],
                             b[nt][0], b[nt][1]);
        }
        __syncthreads();
    }

#pragma unroll
    for (int mt = 0; mt < 4; mt++) {
#pragma unroll
        for (int nt = 0; nt < 4; nt++) {
            int gc = block_n + wn * 32 + nt * 8 + 2 * tig;
            float bx, by;
            if (MODE == 1) {
                bx = (gc < OFF_N) ? bias1[gc] : bias2[gc - OFF_N];
                by = (gc + 1 < OFF_N) ? bias1[gc + 1] : bias2[gc + 1 - OFF_N];
            } else {
                bx = bias1[gc]; by = bias1[gc + 1];
            }
#pragma unroll
            for (int rr = 0; rr < 2; rr++) {
                int gr = block_m + wm * 64 + mt * 16 + tg + rr * 8;
                if (gr >= M) continue;
                float ox = acc[mt][nt][rr * 2 + 0] + bx;
                float oy = acc[mt][nt][rr * 2 + 1] + by;
                if (MODE == 1) {
                    float2 o; o.x = ox; o.y = oy;
                    *reinterpret_cast<float2*>(g_qo + (size_t)gr * QO_N + gc) = o;
                } else {
                    const float2 idv = *reinterpret_cast<const float2*>(addsrc + (size_t)gr * 256 + gc);
                    float2 o; o.x = ox + idv.x; o.y = oy + idv.y;
                    *reinterpret_cast<float2*>(Cext + (size_t)gr * 256 + gc) = o;
                }
            }
        }
    }
}

// ===========================================================================
// Sampling v3 (unchanged).
// ===========================================================================
__global__ __launch_bounds__(256)
void sample_kernel3(const float* __restrict__ ref, const float* __restrict__ lro)
{
    int gwarp = (blockIdx.x * blockDim.x + threadIdx.x) >> 5;
    int lane  = threadIdx.x & 31;
    int hp    = gwarp & 3;
    int bq    = gwarp >> 2;
    if (bq >= BS * NQ) return;
    int b  = bq / NQ;
    int hi = lane >> 4;
    int li = lane & 15;
    int h  = hp * 2 + hi;

    const float* row = g_qo + (size_t)bq * QO_N;

    float logit = row[OFF_N + h * 16 + li];
    float m = logit;
#pragma unroll
    for (int s = 8; s; s >>= 1) m = fmaxf(m, __shfl_xor_sync(0xffffffffu, m, s));
    float e = expf(logit - m);
    float ss = e;
#pragma unroll
    for (int s = 8; s; s >>= 1) ss += __shfl_xor_sync(0xffffffffu, ss, s);
    float a = e / ss;

    int l = li >> 2;
    int p = li & 3;
    int W = c_W[l], H = c_H[l], st = c_start[l];

    float rx = ref[(size_t)(bq * 4 + l) * 2 + 0];
    float ry = ref[(size_t)(bq * 4 + l) * 2 + 1];
    float lx = lro[(size_t)(bq * 8 + h) * 2 + 0];
    float ly = lro[(size_t)(bq * 8 + h) * 2 + 1];
    float ox = row[((h * 4 + l) * 4 + p) * 2 + 0];
    float oy = row[((h * 4 + l) * 4 + p) * 2 + 1];

    float px = (rx + ox * c_invW[l] + lx) * c_Wf[l] - 0.5f;
    float py = (ry + oy * c_invH[l] + ly) * c_Hf[l] - 0.5f;

    float x0f = floorf(px), y0f = floorf(py);
    int   x0  = (int)x0f,   y0  = (int)y0f;
    float wx1 = px - x0f, wx0 = 1.f - wx1;
    float wy1 = py - y0f, wy0 = 1.f - wy1;

    float vx0 = (x0 >= 0 && x0 < W)         ? wx0 : 0.f;
    float vx1 = (x0 + 1 >= 0 && x0 + 1 < W) ? wx1 : 0.f;
    float vy0 = (y0 >= 0 && y0 < H)         ? wy0 : 0.f;
    float vy1 = (y0 + 1 >= 0 && y0 + 1 < H) ? wy1 : 0.f;

    __half2 hAB = __floats2half2_rn(a * vy0 * vx0, a * vy0 * vx1);
    __half2 hCD = __floats2half2_rn(a * vy1 * vx0, a * vy1 * vx1);
    uint32_t uAB = *reinterpret_cast<uint32_t*>(&hAB);
    uint32_t uCD = *reinterpret_cast<uint32_t*>(&hCD);

    int cx0 = min(max(x0, 0), W - 1);
    int cx1 = min(max(x0 + 1, 0), W - 1);
    int cy0 = min(max(y0, 0), H - 1);
    int cy1 = min(max(y0 + 1, 0), H - 1);

    int idxPack = (st + cy0 * W + cx0) * 16
                | ((cx1 - cx0) << 20)
                | ((cy1 - cy0) << 21);

    const __half2* vb2 = reinterpret_cast<const __half2*>(g_v_h)
                       + (size_t)(b * HEADS + h) * (NV * 16) + li;
    float accx = 0.f, accy = 0.f;
    const int srcbase = lane & 16;
    const int Wtab16[4] = {160 * 16, 80 * 16, 40 * 16, 20 * 16};

#pragma unroll
    for (int j = 0; j < 16; j++) {
        int src = srcbase + j;
        uint32_t pAB = __shfl_sync(0xffffffffu, uAB, src);
        uint32_t pCD = __shfl_sync(0xffffffffu, uCD, src);
        int      pk  = __shfl_sync(0xffffffffu, idxPack, src);

        int i00 = pk & 0xFFFFF;
        int dx  = ((pk >> 20) & 1) * 16;
        int dy  = ((pk >> 21) & 1) * Wtab16[j >> 2];

        float2 wab = __half22float2(*reinterpret_cast<const __half2*>(&pAB));
        float2 wcd = __half22float2(*reinterpret_cast<const __half2*>(&pCD));

        float2 f00 = __half22float2(vb2[i00]);
        float2 f10 = __half22float2(vb2[i00 + dx]);
        float2 f01 = __half22float2(vb2[i00 + dy]);
        float2 f11 = __half22float2(vb2[i00 + dx + dy]);

        accx += wab.x * f00.x + wab.y * f10.x + wcd.x * f01.x + wcd.y * f11.x;
        accy += wab.x * f00.y + wab.y * f10.y + wcd.x * f01.y + wcd.y * f11.y;
    }

    float2* outp = reinterpret_cast<float2*>(g_att + (size_t)bq * EMBED + h * DIM) + li;
    *outp = make_float2(accx, accy);
}

// ---------------------------------------------------------------------------
extern "C" void kernel_launch(void* const* d_in, const int* in_sizes, int n_in,
                              void* d_out, int out_size)
{
    (void)in_sizes; (void)n_in; (void)out_size;
    const float* query = (const float*)d_in[0];
    const float* value = (const float*)d_in[1];
    const float* qpos  = (const float*)d_in[2];
    const float* ref   = (const float*)d_in[3];
    const float* lro   = (const float*)d_in[4];
    const float* Wv    = (const float*)d_in[6];
    const float* bv    = (const float*)d_in[7];
    const float* Wo    = (const float*)d_in[8];
    const float* bo    = (const float*)d_in[9];
    const float* Wa    = (const float*)d_in[10];
    const float* ba    = (const float*)d_in[11];
    const float* Wout  = (const float*)d_in[12];
    const float* bout  = (const float*)d_in[13];
    float* out = (float*)d_out;

    // persistent side stream + fork/join events (host objects only)
    static cudaStream_t s2 = nullptr;
    static cudaEvent_t  eFork = nullptr, eJoin = nullptr;
    if (!s2) {
        cudaStreamCreateWithFlags(&s2, cudaStreamNonBlocking);
        cudaEventCreateWithFlags(&eFork, cudaEventDisableTiming);
        cudaEventCreateWithFlags(&eJoin, cudaEventDisableTiming);
    }

    // fork: mode-1 GEMM (independent of value path) on side stream
    cudaEventRecord(eFork, 0);
    cudaStreamWaitEvent(s2, eFork, 0);
    {
        dim3 g(3, (BS * NQ + 127) / 128);
        gemm_tc<1><<<g, 256, 0, s2>>>(query, qpos, Wo, Wa, bo, ba, nullptr, nullptr, BS * NQ);
    }
    cudaEventRecord(eJoin, s2);

    // main stream: value path
    conv_wv<<<128, 256>>>(Wv);
    {
        dim3 g(2, (BS * NV + 127) / 128);
        gemm_v_bf16<<<g, 256>>>(value, bv, BS * NV);
    }

    // join before sampler (needs g_qo and g_v_h)
    cudaStreamWaitEvent(0, eJoin, 0);
    {
        int total_warps = BS * NQ * 4;
        sample_kernel3<<<(total_warps * 32 + 255) / 256, 256>>>(ref, lro);
    }
    {
        dim3 g(2, (BS * NQ + 127) / 128);
        gemm_tc<2><<<g, 256>>>(nullptr, nullptr, Wout, nullptr, bout, nullptr, query, out, BS * NQ);
    }
}

// round 17
// speedup vs baseline: 1.3372x; 1.0435x over previous
#include <cuda_runtime.h>
#include <cuda_fp16.h>
#include <cuda_bf16.h>
#include <math.h>
#include <stdint.h>

#define HEADS  8
#define LEVELS 4
#define POINTS 4
#define DIM    32
#define EMBED  256
#define NQ     1200
#define BS     8
#define NV     19560   // 92*160 + 46*80 + 23*40 + 12*20

#define OFF_N  256
#define QO_N   384

// Scratch (allocation-free rule: device globals)
__device__ __half    g_v_h[(size_t)BS * HEADS * NV * DIM]; // (b,h,pix,d) fp16 : 80 MB
__device__ float     g_qo[(size_t)BS * NQ * QO_N];         // offsets(256) || logits(128)
__device__ float     g_att[(size_t)BS * NQ * EMBED];
__device__ uint32_t  g_wvT[256 * 128];                     // Wv bf16 pairs [n][kk]

__constant__ int   c_H[4]    = {92, 46, 23, 12};
__constant__ int   c_W[4]    = {160, 80, 40, 20};
__constant__ int   c_start[4]= {0, 14720, 18400, 19320};
__constant__ float c_Hf[4]   = {92.f, 46.f, 23.f, 12.f};
__constant__ float c_Wf[4]   = {160.f, 80.f, 40.f, 20.f};
__constant__ float c_invH[4] = {1.f/92.f, 1.f/46.f, 1.f/23.f, 1.f/12.f};
__constant__ float c_invW[4] = {1.f/160.f, 1.f/80.f, 1.f/40.f, 1.f/20.f};

// ---------------------------------------------------------------------------
__global__ __launch_bounds__(256)
void conv_wv(const float* __restrict__ Wv)
{
    int idx = blockIdx.x * 256 + threadIdx.x;
    int n  = idx >> 7;
    int kk = idx & 127;
    float lo = Wv[(size_t)(2 * kk) * 256 + n];
    float hi = Wv[(size_t)(2 * kk + 1) * 256 + n];
    __nv_bfloat162 p = __floats2bfloat162_rn(lo, hi);
    g_wvT[n * 128 + kk] = *reinterpret_cast<uint32_t*>(&p);
}

// ===========================================================================
// bf16 mma.m16n8k16 value GEMM (R16 config: ldmatrix + __ldcs A + coalesced
// staged epilogue).
// ===========================================================================
__device__ __forceinline__ void mma_bf16(float& d0, float& d1, float& d2, float& d3,
                                         uint32_t a0, uint32_t a1, uint32_t a2, uint32_t a3,
                                         uint32_t b0, uint32_t b1) {
    asm volatile("mma.sync.aligned.m16n8k16.row.col.f32.bf16.bf16.f32 "
                 "{%0,%1,%2,%3},{%4,%5,%6,%7},{%8,%9},{%0,%1,%2,%3};"
                 : "+f"(d0), "+f"(d1), "+f"(d2), "+f"(d3)
                 : "r"(a0), "r"(a1), "r"(a2), "r"(a3), "r"(b0), "r"(b1));
}

__device__ __forceinline__ void ldsm_x4(uint32_t& r0, uint32_t& r1, uint32_t& r2, uint32_t& r3,
                                        uint32_t addr) {
    asm volatile("ldmatrix.sync.aligned.m8n8.x4.shared.b16 {%0,%1,%2,%3}, [%4];"
                 : "=r"(r0), "=r"(r1), "=r"(r2), "=r"(r3) : "r"(addr));
}

__device__ __forceinline__ uint32_t smem_u32(const void* p) {
    uint32_t a;
    asm("{ .reg .u64 t; cvta.to.shared.u64 t, %1; cvt.u32.u64 %0, t; }" : "=r"(a) : "l"(p));
    return a;
}

#define PSTRIDE 20   // 16 kpairs + 4 pad (uint32)
#define STG_ROW 40   // staging row stride in halves

__global__ __launch_bounds__(256)
void gemm_v_bf16(const float* __restrict__ A, const float* __restrict__ bias, int M)
{
    __shared__ uint32_t As[128][PSTRIDE];   // [m][kpair]; reused as epilogue staging
    __shared__ uint32_t Bsm[128][PSTRIDE];  // [n][kpair]

    const int tid  = threadIdx.x;
    const int lane = tid & 31;
    const int warp = tid >> 5;
    const int wm   = warp >> 2;
    const int wn   = warp & 3;
    const int tg   = lane >> 2;
    const int tig  = lane & 3;

    const int block_m = blockIdx.y * 128;
    const int block_n = blockIdx.x * 128;

    float acc[4][4][4];
#pragma unroll
    for (int i = 0; i < 4; i++)
#pragma unroll
        for (int j = 0; j < 4; j++)
#pragma unroll
            for (int r = 0; r < 4; r++) acc[i][j][r] = 0.f;

    float4 aS[4];
    uint4  bU[2];

    const int a_row0 = tid >> 3;
    const int a_c4   = (tid & 7) * 4;
    const int b_n    = tid >> 1;
    const int b_s0   = (tid & 1) * 2;

    uint32_t aAddr[4];
    {
        uint32_t base = smem_u32(As);
        int row = wm * 64 + (lane & 15);
        int po  = (lane >> 4) * 4;
#pragma unroll
        for (int mt = 0; mt < 4; mt++)
            aAddr[mt] = base + (uint32_t)(((row + mt * 16) * PSTRIDE + po) * 4);
    }
    uint32_t bAddr[2];
    {
        uint32_t base = smem_u32(Bsm);
        int row = wn * 32 + (lane & 7) + ((lane >> 4) & 1) * 8;
        int po  = ((lane >> 3) & 1) * 4;
#pragma unroll
        for (int g = 0; g < 2; g++)
            bAddr[g] = base + (uint32_t)(((row + g * 16) * PSTRIDE + po) * 4);
    }

    auto ldgA = [&](int k0) {
#pragma unroll
        for (int i = 0; i < 4; i++) {
            int gr = block_m + a_row0 + i * 32;
            float4 v = make_float4(0.f, 0.f, 0.f, 0.f);
            if (gr < M)
                v = __ldcs(reinterpret_cast<const float4*>(A + (size_t)gr * 256 + k0 + a_c4));
            aS[i] = v;
        }
    };
    auto ldgB = [&](int k0) {
        int kk0 = k0 >> 1;
#pragma unroll
        for (int j = 0; j < 2; j++)
            bU[j] = *reinterpret_cast<const uint4*>(
                &g_wvT[(block_n + b_n) * 128 + kk0 + (b_s0 + j) * 4]);
    };
    auto sts = [&]() {
#pragma unroll
        for (int i = 0; i < 4; i++) {
            __nv_bfloat162 p0 = __floats2bfloat162_rn(aS[i].x, aS[i].y);
            __nv_bfloat162 p1 = __floats2bfloat162_rn(aS[i].z, aS[i].w);
            uint2 u;
            u.x = *reinterpret_cast<uint32_t*>(&p0);
            u.y = *reinterpret_cast<uint32_t*>(&p1);
            *reinterpret_cast<uint2*>(&As[a_row0 + i * 32][(a_c4 >> 1)]) = u;
        }
#pragma unroll
        for (int j = 0; j < 2; j++)
            *reinterpret_cast<uint4*>(&Bsm[b_n][(b_s0 + j) * 4]) = bU[j];
    };

    ldgA(0); ldgB(0);

    for (int k0 = 0; k0 < 256; k0 += 32) {
        sts();
        __syncthreads();
        if (k0 + 32 < 256) { ldgA(k0 + 32); ldgB(k0 + 32); }

#pragma unroll
        for (int s = 0; s < 2; s++) {
            const uint32_t soff = (uint32_t)(s * 32);
            uint32_t a[4][4], b[4][2];
#pragma unroll
            for (int mt = 0; mt < 4; mt++)
                ldsm_x4(a[mt][0], a[mt][1], a[mt][2], a[mt][3], aAddr[mt] + soff);
#pragma unroll
            for (int g = 0; g < 2; g++)
                ldsm_x4(b[2 * g][0], b[2 * g][1], b[2 * g + 1][0], b[2 * g + 1][1],
                        bAddr[g] + soff);
#pragma unroll
            for (int mt = 0; mt < 4; mt++)
#pragma unroll
                for (int nt = 0; nt < 4; nt++)
                    mma_bf16(acc[mt][nt][0], acc[mt][nt][1], acc[mt][nt][2], acc[mt][nt][3],
                             a[mt][0], a[mt][1], a[mt][2], a[mt][3],
                             b[nt][0], b[nt][1]);
        }
        __syncthreads();
    }

    // ===== coalesced epilogue =====
    const int head = 4 * blockIdx.x + wn;
    __half* stg = reinterpret_cast<__half*>(As) + warp * (16 * STG_ROW);
    const float bx[4] = { bias[head * 32 + 0 * 8 + 2 * tig], bias[head * 32 + 1 * 8 + 2 * tig],
                          bias[head * 32 + 2 * 8 + 2 * tig], bias[head * 32 + 3 * 8 + 2 * tig] };
    const float by[4] = { bias[head * 32 + 0 * 8 + 2 * tig + 1], bias[head * 32 + 1 * 8 + 2 * tig + 1],
                          bias[head * 32 + 2 * 8 + 2 * tig + 1], bias[head * 32 + 3 * 8 + 2 * tig + 1] };

#pragma unroll
    for (int mt = 0; mt < 4; mt++) {
#pragma unroll
        for (int nt = 0; nt < 4; nt++) {
#pragma unroll
            for (int rr = 0; rr < 2; rr++) {
                int r = tg + rr * 8;
                __half2 v = __floats2half2_rn(acc[mt][nt][rr * 2 + 0] + bx[nt],
                                              acc[mt][nt][rr * 2 + 1] + by[nt]);
                *reinterpret_cast<__half2*>(&stg[r * STG_ROW + nt * 8 + 2 * tig]) = v;
            }
        }
        __syncwarp();
#pragma unroll
        for (int pass = 0; pass < 2; pass++) {
            int t    = pass * 32 + lane;
            int row  = t >> 2;
            int c16  = (t & 3) * 8;
            int pixr = block_m + wm * 64 + mt * 16 + row;
            if (pixr < M) {
                int b = pixr / NV;
                int n = pixr - b * NV;
                uint4 v = *reinterpret_cast<const uint4*>(&stg[row * STG_ROW + c16]);
                *reinterpret_cast<uint4*>(
                    g_v_h + ((size_t)(b * HEADS + head) * NV + n) * DIM + c16) = v;
            }
        }
        __syncwarp();
    }
}

// ===========================================================================
// tf32 mma.sync GEMM for modes 1,2 (unchanged).
// ===========================================================================
__device__ __forceinline__ uint32_t f2tf32(float f) {
    uint32_t u;
    asm("cvt.rna.tf32.f32 %0, %1;" : "=r"(u) : "f"(f));
    return u;
}

__device__ __forceinline__ void mma_tf32(float& d0, float& d1, float& d2, float& d3,
                                         uint32_t a0, uint32_t a1, uint32_t a2, uint32_t a3,
                                         uint32_t b0, uint32_t b1) {
    asm volatile("mma.sync.aligned.m16n8k8.row.col.f32.tf32.tf32.f32 "
                 "{%0,%1,%2,%3},{%4,%5,%6,%7},{%8,%9},{%0,%1,%2,%3};"
                 : "+f"(d0), "+f"(d1), "+f"(d2), "+f"(d3)
                 : "r"(a0), "r"(a1), "r"(a2), "r"(a3), "r"(b0), "r"(b1));
}

#define AS_STRIDE 36
#define BS_STRIDE 136

template <int MODE>
__global__ __launch_bounds__(256)
void gemm_tc(const float* __restrict__ Aext, const float* __restrict__ A2,
             const float* __restrict__ B1,  const float* __restrict__ B2,
             const float* __restrict__ bias1, const float* __restrict__ bias2,
             const float* __restrict__ addsrc, float* __restrict__ Cext, int M)
{
    __shared__ uint32_t As[128][AS_STRIDE];
    __shared__ uint32_t Bsm[32][BS_STRIDE];

    const float* A = (MODE == 2) ? g_att : Aext;

    const int tid  = threadIdx.x;
    const int lane = tid & 31;
    const int warp = tid >> 5;
    const int wm   = warp >> 2;
    const int wn   = warp & 3;
    const int tg   = lane >> 2;
    const int tig  = lane & 3;

    const int block_m = blockIdx.y * 128;
    const int block_n = blockIdx.x * 128;

    float acc[4][4][4];
#pragma unroll
    for (int i = 0; i < 4; i++)
#pragma unroll
        for (int j = 0; j < 4; j++)
#pragma unroll
            for (int r = 0; r < 4; r++) acc[i][j][r] = 0.f;

    float4 aS[4], bS[4];
    const int a_row0 = tid >> 3;
    const int a_c4   = (tid & 7) * 4;
    const int b_k0   = tid >> 5;
    const int b_n4   = lane * 4;

    auto ldgA = [&](int k0) {
#pragma unroll
        for (int i = 0; i < 4; i++) {
            int gr = block_m + a_row0 + i * 32;
            float4 v = make_float4(0.f, 0.f, 0.f, 0.f);
            if (gr < M) {
                v = *reinterpret_cast<const float4*>(A + (size_t)gr * 256 + k0 + a_c4);
                if (MODE == 1) {
                    float4 v2 = *reinterpret_cast<const float4*>(A2 + (size_t)gr * 256 + k0 + a_c4);
                    v.x += v2.x; v.y += v2.y; v.z += v2.z; v.w += v2.w;
                }
            }
            aS[i] = v;
        }
    };
    auto ldgB = [&](int k0) {
#pragma unroll
        for (int i = 0; i < 4; i++) {
            int krow = b_k0 + i * 8;
            int gc   = block_n + b_n4;
            float4 v;
            if (MODE == 1) {
                if (gc < OFF_N) v = *reinterpret_cast<const float4*>(B1 + (size_t)(k0 + krow) * OFF_N + gc);
                else            v = *reinterpret_cast<const float4*>(B2 + (size_t)(k0 + krow) * 128 + (gc - OFF_N));
            } else {
                v = *reinterpret_cast<const float4*>(B1 + (size_t)(k0 + krow) * 256 + gc);
            }
            bS[i] = v;
        }
    };
    auto sts = [&]() {
#pragma unroll
        for (int i = 0; i < 4; i++) {
            uint4 u;
            u.x = f2tf32(aS[i].x); u.y = f2tf32(aS[i].y);
            u.z = f2tf32(aS[i].z); u.w = f2tf32(aS[i].w);
            *reinterpret_cast<uint4*>(&As[a_row0 + i * 32][a_c4]) = u;
        }
#pragma unroll
        for (int i = 0; i < 4; i++) {
            uint4 u;
            u.x = f2tf32(bS[i].x); u.y = f2tf32(bS[i].y);
            u.z = f2tf32(bS[i].z); u.w = f2tf32(bS[i].w);
            *reinterpret_cast<uint4*>(&Bsm[b_k0 + i * 8][b_n4]) = u;
        }
    };

    ldgA(0); ldgB(0);

    for (int k0 = 0; k0 < 256; k0 += 32) {
        sts();
        __syncthreads();
        if (k0 + 32 < 256) { ldgA(k0 + 32); ldgB(k0 + 32); }

#pragma unroll
        for (int ks = 0; ks < 4; ks++) {
            const int k = ks * 8;
            uint32_t a[4][4], b[4][2];
#pragma unroll
            for (int mt = 0; mt < 4; mt++) {
                int m = wm * 64 + mt * 16 + tg;
                a[mt][0] = As[m][k + tig];
                a[mt][1] = As[m + 8][k + tig];
                a[mt][2] = As[m][k + tig + 4];
                a[mt][3] = As[m + 8][k + tig + 4];
            }
#pragma unroll
            for (int nt = 0; nt < 4; nt++) {
                int n = wn * 32 + nt * 8 + tg;
                b[nt][0] = Bsm[k + tig][n];
                b[nt][1] = Bsm[k + tig + 4][n];
            }
#pragma unroll
            for (int mt = 0; mt < 4; mt++)
#pragma unroll
                for (int nt = 0; nt < 4; nt++)
                    mma_tf32(acc[mt][nt][0], acc[mt][nt][1], acc[mt][nt][2], acc[mt][nt][3],
                             a[mt][0], a[mt][1], a[mt][2], a[mt][3],
                             b[nt][0], b[nt][1]);
        }
        __syncthreads();
    }

#pragma unroll
    for (int mt = 0; mt < 4; mt++) {
#pragma unroll
        for (int nt = 0; nt < 4; nt++) {
            int gc = block_n + wn * 32 + nt * 8 + 2 * tig;
            float bx, by;
            if (MODE == 1) {
                bx = (gc < OFF_N) ? bias1[gc] : bias2[gc - OFF_N];
                by = (gc + 1 < OFF_N) ? bias1[gc + 1] : bias2[gc + 1 - OFF_N];
            } else {
                bx = bias1[gc]; by = bias1[gc + 1];
            }
#pragma unroll
            for (int rr = 0; rr < 2; rr++) {
                int gr = block_m + wm * 64 + mt * 16 + tg + rr * 8;
                if (gr >= M) continue;
                float ox = acc[mt][nt][rr * 2 + 0] + bx;
                float oy = acc[mt][nt][rr * 2 + 1] + by;
                if (MODE == 1) {
                    float2 o; o.x = ox; o.y = oy;
                    *reinterpret_cast<float2*>(g_qo + (size_t)gr * QO_N + gc) = o;
                } else {
                    const float2 idv = *reinterpret_cast<const float2*>(addsrc + (size_t)gr * 256 + gc);
                    float2 o; o.x = ox + idv.x; o.y = oy + idv.y;
                    *reinterpret_cast<float2*>(Cext + (size_t)gr * 256 + gc) = o;
                }
            }
        }
    }
}

// ===========================================================================
// Sampling v4: 8-byte gathers + point-pairing.
// Warp = (bq, head-pair). Half-warp hi = head. Within a half-warp:
// s = (lane>>3)&1 selects point parity, q = lane&7 selects 4-channel quad.
// Per iteration jj (0..7) the half-warp processes points 2*jj and 2*jj+1.
// Phase A (per-lane point params, lane li = lane&15) is unchanged from v3.
// ===========================================================================
__global__ __launch_bounds__(256)
void sample_kernel4(const float* __restrict__ ref, const float* __restrict__ lro)
{
    int gwarp = (blockIdx.x * blockDim.x + threadIdx.x) >> 5;
    int lane  = threadIdx.x & 31;
    int hp    = gwarp & 3;
    int bq    = gwarp >> 2;
    if (bq >= BS * NQ) return;
    int b  = bq / NQ;
    int hi = lane >> 4;
    int li = lane & 15;
    int h  = hp * 2 + hi;

    const float* row = g_qo + (size_t)bq * QO_N;

    // ---- softmax over 16 logits, per half-warp (lane li holds logit li) ----
    float logit = row[OFF_N + h * 16 + li];
    float m = logit;
#pragma unroll
    for (int s = 8; s; s >>= 1) m = fmaxf(m, __shfl_xor_sync(0xffffffffu, m, s));
    float e = expf(logit - m);
    float ss = e;
#pragma unroll
    for (int s = 8; s; s >>= 1) ss += __shfl_xor_sync(0xffffffffu, ss, s);
    float a = e / ss;

    // ---- phase A: per-lane point li params ----
    int l = li >> 2;
    int p = li & 3;
    int W = c_W[l], H = c_H[l], st = c_start[l];

    float rx = ref[(size_t)(bq * 4 + l) * 2 + 0];
    float ry = ref[(size_t)(bq * 4 + l) * 2 + 1];
    float lx = lro[(size_t)(bq * 8 + h) * 2 + 0];
    float ly = lro[(size_t)(bq * 8 + h) * 2 + 1];
    float ox = row[((h * 4 + l) * 4 + p) * 2 + 0];
    float oy = row[((h * 4 + l) * 4 + p) * 2 + 1];

    float px = (rx + ox * c_invW[l] + lx) * c_Wf[l] - 0.5f;
    float py = (ry + oy * c_invH[l] + ly) * c_Hf[l] - 0.5f;

    float x0f = floorf(px), y0f = floorf(py);
    int   x0  = (int)x0f,   y0  = (int)y0f;
    float wx1 = px - x0f, wx0 = 1.f - wx1;
    float wy1 = py - y0f, wy0 = 1.f - wy1;

    float vx0 = (x0 >= 0 && x0 < W)         ? wx0 : 0.f;
    float vx1 = (x0 + 1 >= 0 && x0 + 1 < W) ? wx1 : 0.f;
    float vy0 = (y0 >= 0 && y0 < H)         ? wy0 : 0.f;
    float vy1 = (y0 + 1 >= 0 && y0 + 1 < H) ? wy1 : 0.f;

    __half2 hAB = __floats2half2_rn(a * vy0 * vx0, a * vy0 * vx1);
    __half2 hCD = __floats2half2_rn(a * vy1 * vx0, a * vy1 * vx1);
    uint32_t uAB = *reinterpret_cast<uint32_t*>(&hAB);
    uint32_t uCD = *reinterpret_cast<uint32_t*>(&hCD);

    int cx0 = min(max(x0, 0), W - 1);
    int cx1 = min(max(x0 + 1, 0), W - 1);
    int cy0 = min(max(y0, 0), H - 1);
    int cy1 = min(max(y0 + 1, 0), H - 1);

    // index in float2 (8B) units: pixel*8. bit 20 = dx flag, bit 21 = dy flag
    int idxPack = (st + cy0 * W + cx0) * 8
                | ((cx1 - cx0) << 20)
                | ((cy1 - cy0) << 21);

    // ---- phase B: 8 iterations, 2 points per half-warp per iteration ----
    const int q = lane & 7;                        // channel quad (4 channels)
    const uint2* vb = reinterpret_cast<const uint2*>(g_v_h)
                    + (size_t)(b * HEADS + h) * (NV * 8) + q;
    const int srcb = (lane & 16) + ((lane >> 3) & 1);   // phase-A lane of my point
    const int W8tab[4] = {160 * 8, 80 * 8, 40 * 8, 20 * 8};

    float acc0 = 0.f, acc1 = 0.f, acc2 = 0.f, acc3 = 0.f;

#pragma unroll
    for (int jj = 0; jj < 8; jj++) {
        int src = srcb + 2 * jj;
        uint32_t pAB = __shfl_sync(0xffffffffu, uAB, src);
        uint32_t pCD = __shfl_sync(0xffffffffu, uCD, src);
        int      pk  = __shfl_sync(0xffffffffu, idxPack, src);

        int i00 = pk & 0xFFFFF;
        int dx  = ((pk >> 20) & 1) * 8;
        int dy  = ((pk >> 21) & 1) * W8tab[jj >> 1];   // level = (2jj+s)>>2 = jj>>1

        float2 wab = __half22float2(*reinterpret_cast<const __half2*>(&pAB));
        float2 wcd = __half22float2(*reinterpret_cast<const __half2*>(&pCD));

        uint2 u00 = vb[i00];
        uint2 u10 = vb[i00 + dx];
        uint2 u01 = vb[i00 + dy];
        uint2 u11 = vb[i00 + dx + dy];

        float2 a00 = __half22float2(*reinterpret_cast<const __half2*>(&u00.x));
        float2 b00 = __half22float2(*reinterpret_cast<const __half2*>(&u00.y));
        float2 a10 = __half22float2(*reinterpret_cast<const __half2*>(&u10.x));
        float2 b10 = __half22float2(*reinterpret_cast<const __half2*>(&u10.y));
        float2 a01 = __half22float2(*reinterpret_cast<const __half2*>(&u01.x));
        float2 b01 = __half22float2(*reinterpret_cast<const __half2*>(&u01.y));
        float2 a11 = __half22float2(*reinterpret_cast<const __half2*>(&u11.x));
        float2 b11 = __half22float2(*reinterpret_cast<const __half2*>(&u11.y));

        acc0 += wab.x * a00.x + wab.y * a10.x + wcd.x * a01.x + wcd.y * a11.x;
        acc1 += wab.x * a00.y + wab.y * a10.y + wcd.x * a01.y + wcd.y * a11.y;
        acc2 += wab.x * b00.x + wab.y * b10.x + wcd.x * b01.x + wcd.y * b11.x;
        acc3 += wab.x * b00.y + wab.y * b10.y + wcd.x * b01.y + wcd.y * b11.y;
    }

    // ---- cross-parity reduction (s=0 lane += s=1 lane) ----
    acc0 += __shfl_down_sync(0xffffffffu, acc0, 8);
    acc1 += __shfl_down_sync(0xffffffffu, acc1, 8);
    acc2 += __shfl_down_sync(0xffffffffu, acc2, 8);
    acc3 += __shfl_down_sync(0xffffffffu, acc3, 8);

    if (!(lane & 8)) {
        float4 o; o.x = acc0; o.y = acc1; o.z = acc2; o.w = acc3;
        *reinterpret_cast<float4*>(g_att + (size_t)bq * EMBED + h * DIM + q * 4) = o;
    }
}

// ---------------------------------------------------------------------------
extern "C" void kernel_launch(void* const* d_in, const int* in_sizes, int n_in,
                              void* d_out, int out_size)
{
    (void)in_sizes; (void)n_in; (void)out_size;
    const float* query = (const float*)d_in[0];
    const float* value = (const float*)d_in[1];
    const float* qpos  = (const float*)d_in[2];
    const float* ref   = (const float*)d_in[3];
    const float* lro   = (const float*)d_in[4];
    const float* Wv    = (const float*)d_in[6];
    const float* bv    = (const float*)d_in[7];
    const float* Wo    = (const float*)d_in[8];
    const float* bo    = (const float*)d_in[9];
    const float* Wa    = (const float*)d_in[10];
    const float* ba    = (const float*)d_in[11];
    const float* Wout  = (const float*)d_in[12];
    const float* bout  = (const float*)d_in[13];
    float* out = (float*)d_out;

    // persistent side stream + fork/join events (host objects only)
    static cudaStream_t s2 = nullptr;
    static cudaEvent_t  eFork = nullptr, eJoin = nullptr;
    if (!s2) {
        cudaStreamCreateWithFlags(&s2, cudaStreamNonBlocking);
        cudaEventCreateWithFlags(&eFork, cudaEventDisableTiming);
        cudaEventCreateWithFlags(&eJoin, cudaEventDisableTiming);
    }

    // fork: mode-1 GEMM on side stream (hidden under the value path)
    cudaEventRecord(eFork, 0);
    cudaStreamWaitEvent(s2, eFork, 0);
    {
        dim3 g(3, (BS * NQ + 127) / 128);
        gemm_tc<1><<<g, 256, 0, s2>>>(query, qpos, Wo, Wa, bo, ba, nullptr, nullptr, BS * NQ);
    }
    cudaEventRecord(eJoin, s2);

    // main stream: value path
    conv_wv<<<128, 256>>>(Wv);
    {
        dim3 g(2, (BS * NV + 127) / 128);
        gemm_v_bf16<<<g, 256>>>(value, bv, BS * NV);
    }

    // join before sampler (needs g_qo and g_v_h)
    cudaStreamWaitEvent(0, eJoin, 0);
    {
        int total_warps = BS * NQ * 4;
        sample_kernel4<<<(total_warps * 32 + 255) / 256, 256>>>(ref, lro);
    }
    {
        dim3 g(2, (BS * NQ + 127) / 128);
        gemm_tc<2><<<g, 256>>>(nullptr, nullptr, Wout, nullptr, bout, nullptr, query, out, BS * NQ);
    }
}